// round 12
// baseline (speedup 1.0000x reference)
#include <cuda_runtime.h>
#include <cuda_fp16.h>
#include <math.h>
#include <stdint.h>

#define BB 8
#define HH 64
#define WW 64
#define HWSZ 4096
#define CI 128
#define CQ 16
#define CIN 512

// ---------------- scratch buffers (static device allocations) ----------------
__device__ float g_featA[BB*CI*HWSZ];
__device__ float g_featB[BB*CI*HWSZ];
__device__ float g_q [BB*CQ*HWSZ];
__device__ float g_k [BB*CQ*HWSZ];
__device__ float g_kt[BB*CQ*HWSZ];
__device__ float g_v [BB*CI*HWSZ];
__device__ float g_vt[BB*CI*HWSZ];
__device__ uint4 g_att4[(8ULL*HH*WW*128*2)/16];   // fp16 att [b,h,w][128]

// padded NHWC fp16 feature maps (16B aligned via uint4)
#define XP640_ELEMS (8ULL*66*66*640)
#define XP128_ELEMS (8ULL*66*66*128)
#define WSP_ELEMS   (9ULL*512*640)
__device__ uint4 g_xph4[XP640_ELEMS/8];
__device__ uint4 g_x2h4[XP128_ELEMS/8];
__device__ uint4 g_whi4[WSP_ELEMS/8];
__device__ uint4 g_wqkv4[(256*128)/8];   // packed q|k|v|pad weights, fp16

// =====================================================================
// PTX helpers (compute_103-safe: mma.sync / ldmatrix / cp.async only)
// =====================================================================
__device__ __forceinline__ uint32_t smem_u32(const void* p) {
    uint32_t a;
    asm("{ .reg .u64 t; cvta.to.shared.u64 t, %1; cvt.u32.u64 %0, t; }" : "=r"(a) : "l"(p));
    return a;
}
__device__ __forceinline__ void cpa16(uint32_t dst, const void* src) {
    asm volatile("cp.async.cg.shared.global [%0], [%1], 16;" :: "r"(dst), "l"(src) : "memory");
}
__device__ __forceinline__ void cpa_commit() {
    asm volatile("cp.async.commit_group;" ::: "memory");
}
__device__ __forceinline__ void cpa_wait1() {
    asm volatile("cp.async.wait_group 1;" ::: "memory");
}
__device__ __forceinline__ void cpa_wait0() {
    asm volatile("cp.async.wait_group 0;" ::: "memory");
}
__device__ __forceinline__ void ldsm4(uint32_t* r, uint32_t addr) {
    asm volatile("ldmatrix.sync.aligned.m8n8.x4.shared.b16 {%0,%1,%2,%3}, [%4];"
                 : "=r"(r[0]), "=r"(r[1]), "=r"(r[2]), "=r"(r[3]) : "r"(addr));
}
__device__ __forceinline__ void mma16816(float* c, const uint32_t* a, const uint32_t* b) {
    asm volatile(
        "mma.sync.aligned.m16n8k16.row.col.f32.f16.f16.f32 "
        "{%0,%1,%2,%3}, {%4,%5,%6,%7}, {%8,%9}, {%0,%1,%2,%3};"
        : "+f"(c[0]), "+f"(c[1]), "+f"(c[2]), "+f"(c[3])
        : "r"(a[0]), "r"(a[1]), "r"(a[2]), "r"(a[3]), "r"(b[0]), "r"(b[1]));
}
__device__ __forceinline__ uint32_t sw128(uint32_t off) {
    return off ^ ((off >> 3) & 0x70);
}
__device__ __forceinline__ uint4 pack8h(const float* f) {
    __half2 h0 = __floats2half2_rn(f[0], f[1]);
    __half2 h1 = __floats2half2_rn(f[2], f[3]);
    __half2 h2 = __floats2half2_rn(f[4], f[5]);
    __half2 h3 = __floats2half2_rn(f[6], f[7]);
    uint4 u;
    u.x = *(uint32_t*)&h0; u.y = *(uint32_t*)&h1;
    u.z = *(uint32_t*)&h2; u.w = *(uint32_t*)&h3;
    return u;
}

// =====================================================================
// prep: NCHW fp32 -> padded NHWC fp16 (interior only)
// =====================================================================
__global__ void __launch_bounds__(256) pad_k(
    const float* __restrict__ src, int C,
    __half* __restrict__ dh, int pitch, int colofs)
{
    __shared__ float s[64][65];
    const int y = blockIdx.x, cbase = blockIdx.y * 64, b = blockIdx.z;
    const int t = threadIdx.x;
    for (int idx = t; idx < 4096; idx += 256) {
        int icl = idx >> 6, x = idx & 63;
        s[icl][x] = src[((size_t)(b*C + cbase + icl)*64 + y)*64 + x];
    }
    __syncthreads();
    for (int idx = t; idx < 4096; idx += 256) {
        int x = idx >> 6, icl = idx & 63;
        size_t o = ((size_t)(b*66 + y + 1)*66 + (x + 1))*pitch + colofs + cbase + icl;
        dh[o] = __float2half_rn(s[icl][x]);
    }
}

__global__ void __launch_bounds__(256) zero_border_k(
    __half* __restrict__ dh, int pitch)
{
    const int total = 8 * 260 * pitch;
    for (int idx = blockIdx.x*256 + threadIdx.x; idx < total; idx += gridDim.x*256) {
        int ic = idx % pitch;
        int r  = idx / pitch;
        int b  = r / 260;
        int pos = r % 260;
        int yy, xx;
        if      (pos < 66)  { yy = 0;  xx = pos; }
        else if (pos < 132) { yy = 65; xx = pos - 66; }
        else if (pos < 196) { yy = pos - 132 + 1; xx = 0; }
        else                { yy = pos - 196 + 1; xx = 65; }
        dh[((size_t)(b*66 + yy)*66 + xx)*pitch + ic] = __float2half_rn(0.f);
    }
}

// weights: w[oc][ic][3][3] fp32 -> Wh [tap][oc][ic] fp16
__global__ void __launch_bounds__(256) wprep_k(
    const float* __restrict__ w, int Cout, int Ctot,
    __half* __restrict__ wh)
{
    const int total = Cout * Ctot * 9;
    for (int idx = blockIdx.x*256 + threadIdx.x; idx < total; idx += gridDim.x*256) {
        int ic  = idx % Ctot;
        int r   = idx / Ctot;
        int oc  = r % Cout;
        int tap = r / Cout;
        wh[(size_t)(tap*Cout + oc)*Ctot + ic] =
            __float2half_rn(w[(size_t)(oc*Ctot + ic)*9 + tap]);
    }
}

// packed qkv weights: [256 oc][128 ic] fp16 = q(16) | k(16) | v(128) | zeros(96)
__global__ void __launch_bounds__(256) wprep_qkv_k(
    const float* __restrict__ wq, const float* __restrict__ wk,
    const float* __restrict__ wv, __half* __restrict__ wh)
{
    const int total = 256 * 128;
    for (int idx = blockIdx.x*256 + threadIdx.x; idx < total; idx += gridDim.x*256) {
        int oc = idx >> 7, ic = idx & 127;
        float v = 0.f;
        if      (oc < 16)  v = wq[oc*128 + ic];
        else if (oc < 32)  v = wk[(oc-16)*128 + ic];
        else if (oc < 160) v = wv[(oc-32)*128 + ic];
        wh[idx] = __float2half_rn(v);
    }
}

// =====================================================================
// HMMA implicit-GEMM conv (frozen R7/R11 structure).
// modes: 0 = BN, 1 = ELU(512), 3 = qkv scatter (q, k, v + vt)
// =====================================================================
#define TILE_B (128*128)
#define OFF_A  0
#define OFF_B  TILE_B
#define STAGE_B (2*TILE_B)
#define SM_TOTAL (3*STAGE_B)

__global__ void __launch_bounds__(256, 2) convmma_k(
    const __half* __restrict__ Xh,
    int pitch, int chunks, int ntap,
    const __half* __restrict__ Wh,
    int Ctot, int Cout,
    const float* __restrict__ p0, const float* __restrict__ p1,
    const float* __restrict__ p2, const float* __restrict__ p3,
    float* __restrict__ out, int mode,
    float* __restrict__ out2, float* __restrict__ out3,
    float* __restrict__ out3t)
{
    extern __shared__ __align__(128) char smem[];
    const uint32_t sb = smem_u32(smem);
    const int t = threadIdx.x;
    const int warp = t >> 5, lane = t & 31;
    const int nog = Cout >> 7;
    const int ocg = blockIdx.y % nog;
    const int b   = blockIdx.y / nog;
    const int y0  = blockIdx.x * 2;
    const int ocb = ocg * 128;

    const int q8 = t & 7;
    const int r0 = t >> 3;

    const int T = chunks * ntap;

    auto issue_tile = [&](int i) {
        const int c   = i / ntap;
        const int tap = i - c*ntap;
        const int dy  = (ntap == 1) ? 1 : tap / 3;
        const int dx  = (ntap == 1) ? 1 : tap - (tap/3)*3;
        const int ic0 = c * 64;
        const uint32_t base = sb + (uint32_t)(i % 3) * STAGE_B;
        #pragma unroll
        for (int p = 0; p < 4; p++) {
            const int m = r0 + 32*p;
            const uint32_t so = sw128((uint32_t)(m*128 + q8*16));
            cpa16(base + OFF_A + so,
                  Wh + (size_t)(tap*Cout + ocb + m)*Ctot + ic0 + q8*8);
            const int yl = m >> 6, x = m & 63;
            cpa16(base + OFF_B + so,
                  Xh + ((size_t)(b*66 + y0 + yl + dy)*66 + (x + dx))*pitch + ic0 + q8*8);
        }
        cpa_commit();
    };

    const int m0 = (warp >> 2) * 64;
    const int n0 = (warp & 3) * 32;
    float acc[4][4][4];
    #pragma unroll
    for (int mi = 0; mi < 4; mi++)
        #pragma unroll
        for (int nj = 0; nj < 4; nj++)
            #pragma unroll
            for (int u = 0; u < 4; u++) acc[mi][nj][u] = 0.f;

    const int arow  = lane & 15;
    const int acolb = ((lane >> 4) << 3) * 2;
    const int brow  = (lane & 7) + ((lane >> 4) << 3);
    const int bcolb = (((lane >> 3) & 1) << 3) * 2;

    issue_tile(0);
    if (T > 1) issue_tile(1);

    for (int i = 0; i < T; i++) {
        if (i + 1 < T) cpa_wait1();
        else           cpa_wait0();
        __syncthreads();
        if (i + 2 < T) issue_tile(i + 2);

        const uint32_t base = sb + (uint32_t)(i % 3) * STAGE_B;
        const uint32_t sA = base + OFF_A;
        const uint32_t sB = base + OFF_B;

        #pragma unroll
        for (int kk = 0; kk < 4; kk++) {
            const int k0b = kk * 32;
            uint32_t a[4][4], bh[2][4];
            #pragma unroll
            for (int mi = 0; mi < 4; mi++) {
                const uint32_t ro = sw128((uint32_t)((m0 + mi*16 + arow) * 128 + k0b + acolb));
                ldsm4(a[mi], sA + ro);
            }
            #pragma unroll
            for (int ni = 0; ni < 2; ni++) {
                const uint32_t ro = sw128((uint32_t)((n0 + ni*16 + brow) * 128 + k0b + bcolb));
                ldsm4(bh[ni], sB + ro);
            }
            #pragma unroll
            for (int mi = 0; mi < 4; mi++)
                #pragma unroll
                for (int nj = 0; nj < 4; nj++)
                    mma16816(acc[mi][nj], a[mi], &bh[nj >> 1][(nj & 1) * 2]);
        }
    }

    // ---- epilogue ----
    const int g  = lane >> 2;
    const int t2 = (lane & 3) * 2;
    #pragma unroll
    for (int mi = 0; mi < 4; mi++) {
        const int ocA = ocb + m0 + mi*16 + g;
        const int ocB = ocA + 8;
        float scA = 1.f, biA = 0.f, scB = 1.f, biB = 0.f;
        if (mode == 0) {
            scA = p0[ocA] * rsqrtf(p3[ocA] + 1e-5f);
            biA = p1[ocA] - p2[ocA] * scA;
            scB = p0[ocB] * rsqrtf(p3[ocB] + 1e-5f);
            biB = p1[ocB] - p2[ocB] * scB;
        }
        #pragma unroll
        for (int nj = 0; nj < 4; nj++) {
            const int n  = n0 + nj*8 + t2;
            const int yl = n >> 6, x = n & 63;
            const int py = y0 + yl;
            float v0 = acc[mi][nj][0], v1 = acc[mi][nj][1];
            float v2 = acc[mi][nj][2], v3 = acc[mi][nj][3];
            if (mode == 3) {
                #pragma unroll
                for (int h = 0; h < 2; h++) {
                    const int oc = h ? ocB : ocA;
                    float u0 = h ? v2 : v0;
                    float u1 = h ? v3 : v1;
                    if (oc < 16) {
                        float bi = p0[oc];
                        *(float2*)&out[((size_t)(b*CQ + oc)*64 + py)*64 + x] =
                            make_float2(u0 + bi, u1 + bi);
                    } else if (oc < 32) {
                        float bi = p1[oc - 16];
                        *(float2*)&out2[((size_t)(b*CQ + oc - 16)*64 + py)*64 + x] =
                            make_float2(u0 + bi, u1 + bi);
                    } else if (oc < 160) {
                        const int c = oc - 32;
                        float bi = p2[c];
                        u0 += bi; u1 += bi;
                        *(float2*)&out3[((size_t)(b*CI + c)*64 + py)*64 + x] =
                            make_float2(u0, u1);
                        out3t[((size_t)(b*CI + c)*64 + x    )*64 + py] = u0;
                        out3t[((size_t)(b*CI + c)*64 + x + 1)*64 + py] = u1;
                    }
                }
                continue;
            }
            if (mode == 0) {
                v0 = v0*scA + biA; v1 = v1*scA + biA;
                v2 = v2*scB + biB; v3 = v3*scB + biB;
            } else {
                if (v0 <= 0.f) v0 = 512.0f * expm1f(v0);
                if (v1 <= 0.f) v1 = 512.0f * expm1f(v1);
                if (v2 <= 0.f) v2 = 512.0f * expm1f(v2);
                if (v3 <= 0.f) v3 = 512.0f * expm1f(v3);
            }
            *(float2*)&out[((size_t)(b*Cout + ocA)*64 + py)*64 + x] = make_float2(v0, v1);
            *(float2*)&out[((size_t)(b*Cout + ocB)*64 + py)*64 + x] = make_float2(v2, v3);
        }
    }
}

// =====================================================================
// attention: trans_k (kt), att_k (logits+softmax -> fp16 att)
// =====================================================================
__global__ void __launch_bounds__(256) trans_k(const float* __restrict__ in,
                                               float* __restrict__ out)
{
    __shared__ float s[64][65];
    const float* src = in  + (size_t)blockIdx.x * 4096;
    float*       dst = out + (size_t)blockIdx.x * 4096;
    for (int idx = threadIdx.x; idx < 4096; idx += 256)
        s[idx >> 6][idx & 63] = src[idx];
    __syncthreads();
    for (int idx = threadIdx.x; idx < 4096; idx += 256)
        dst[idx] = s[idx & 63][idx >> 6];
}

__global__ void __launch_bounds__(256) att_k(
    const float* __restrict__ q, const float* __restrict__ k,
    const float* __restrict__ kt, __half* __restrict__ att)
{
    __shared__ float qs[16*64];
    __shared__ float ks[16*64];
    __shared__ float E[64*128];

    const int t = threadIdx.x;
    const int h = blockIdx.x, b = blockIdx.y;

    for (int idx = t; idx < 1024; idx += 256) {
        int c = idx >> 6, w = idx & 63;
        qs[idx] = q[((b*CQ + c)*HH + h)*WW + w];
        ks[idx] = k[((b*CQ + c)*HH + h)*WW + w];
    }
    __syncthreads();

    for (int idx = t; idx < 2048; idx += 256) {
        const int w  = idx >> 5;
        const int j4 = idx & 31;
        float4 e = make_float4(0.f, 0.f, 0.f, 0.f);
        if (j4 < 16) {
            for (int c = 0; c < 16; c++) {
                float qq = qs[c*64 + w];
                float4 kv = ((const float4*)kt)[((b*CQ + c)*WW + w)*16 + j4];
                e.x += qq * kv.x; e.y += qq * kv.y; e.z += qq * kv.z; e.w += qq * kv.w;
            }
            if ((h >> 2) == j4) ((float*)&e)[h & 3] = -INFINITY;
        } else {
            for (int c = 0; c < 16; c++) {
                float qq = qs[c*64 + w];
                float4 kv = ((const float4*)ks)[c*16 + (j4 - 16)];
                e.x += qq * kv.x; e.y += qq * kv.y; e.z += qq * kv.z; e.w += qq * kv.w;
            }
        }
        ((float4*)E)[w*32 + j4] = e;
    }
    __syncthreads();

    const int lane = t & 31, wid = t >> 5;
    for (int r = 0; r < 8; r++) {
        const int w = wid*8 + r;
        float v0 = E[w*128 + lane],      v1 = E[w*128 + lane + 32];
        float v2 = E[w*128 + lane + 64], v3 = E[w*128 + lane + 96];
        float m = fmaxf(fmaxf(v0, v1), fmaxf(v2, v3));
        #pragma unroll
        for (int s = 16; s; s >>= 1) m = fmaxf(m, __shfl_xor_sync(0xffffffffu, m, s));
        float e0 = expf(v0 - m), e1 = expf(v1 - m), e2 = expf(v2 - m), e3 = expf(v3 - m);
        float sum = e0 + e1 + e2 + e3;
        #pragma unroll
        for (int s = 16; s; s >>= 1) sum += __shfl_xor_sync(0xffffffffu, sum, s);
        float inv = 1.f / sum;
        __half* dst = att + (size_t)((b*HH + h)*WW + w)*128;
        dst[lane]      = __float2half_rn(e0*inv);
        dst[lane + 32] = __float2half_rn(e1*inv);
        dst[lane + 64] = __float2half_rn(e2*inv);
        dst[lane + 96] = __float2half_rn(e3*inv);
    }
}

// =====================================================================
// oWmma_k: per (b,h): C[c][w] = sum_wp v[c,wp] * aW[w,wp] via HMMA;
//          G = feat + gamma*C.
// oHmma_k: per (b,w): C[c][h] = sum_g vt[c,g] * aH[h,g] via HMMA;
//          G += gamma*C.
// Shared smem geometry: Va 128 rows x 128B (fp16, sw128), Aw 64 rows x 128B.
// =====================================================================
#define AGG_VA   0
#define AGG_AW   16384
#define AGG_SMEM (16384 + 8192)

__global__ void __launch_bounds__(256) oWmma_k(
    const __half* __restrict__ att, const float* __restrict__ v,
    const float* __restrict__ feat, const float* __restrict__ gamma,
    float* __restrict__ G)
{
    extern __shared__ __align__(128) char smem[];
    const uint32_t sb = smem_u32(smem);
    const int t = threadIdx.x;
    const int warp = t >> 5, lane = t & 31;
    const int h = blockIdx.x, b = blockIdx.y;

    // Va[c][wp] <- fp16(v[b,c,h,wp])
    for (int idx = t; idx < 1024; idx += 256) {
        const int c = idx >> 3, qq = idx & 7;
        float f[8];
        *(float4*)&f[0] = *(const float4*)(v + ((size_t)(b*CI + c)*64 + h)*64 + qq*8);
        *(float4*)&f[4] = *(const float4*)(v + ((size_t)(b*CI + c)*64 + h)*64 + qq*8 + 4);
        *(uint4*)(smem + AGG_VA + sw128((uint32_t)(c*128 + qq*16))) = pack8h(f);
    }
    // Aw[w][wp] <- att[b,h,w][64+wp]
    for (int idx = t; idx < 512; idx += 256) {
        const int w = idx >> 3, qq = idx & 7;
        uint4 u = *(const uint4*)(att + (size_t)((b*HH + h)*WW + w)*128 + 64 + qq*8);
        *(uint4*)(smem + AGG_AW + sw128((uint32_t)(w*128 + qq*16))) = u;
    }
    __syncthreads();

    const int m0 = (warp >> 2) * 64;
    const int n0 = (warp & 3) * 16;
    float acc[4][2][4];
    #pragma unroll
    for (int mi = 0; mi < 4; mi++)
        #pragma unroll
        for (int nj = 0; nj < 2; nj++)
            #pragma unroll
            for (int u = 0; u < 4; u++) acc[mi][nj][u] = 0.f;

    const int arow  = lane & 15;
    const int acolb = ((lane >> 4) << 3) * 2;
    const int brow  = (lane & 7) + ((lane >> 4) << 3);
    const int bcolb = (((lane >> 3) & 1) << 3) * 2;

    #pragma unroll
    for (int kk = 0; kk < 4; kk++) {
        const int k0b = kk * 32;
        uint32_t a[4][4], bh[4];
        #pragma unroll
        for (int mi = 0; mi < 4; mi++)
            ldsm4(a[mi], sb + AGG_VA + sw128((uint32_t)((m0 + mi*16 + arow)*128 + k0b + acolb)));
        ldsm4(bh, sb + AGG_AW + sw128((uint32_t)((n0 + brow)*128 + k0b + bcolb)));
        #pragma unroll
        for (int mi = 0; mi < 4; mi++)
            #pragma unroll
            for (int nj = 0; nj < 2; nj++)
                mma16816(acc[mi][nj], a[mi], &bh[nj*2]);
    }

    const float gm = gamma[0];
    const int g  = lane >> 2;
    const int t2 = (lane & 3) * 2;
    #pragma unroll
    for (int mi = 0; mi < 4; mi++) {
        const int cA = m0 + mi*16 + g;
        const int cB = cA + 8;
        #pragma unroll
        for (int nj = 0; nj < 2; nj++) {
            const int n = n0 + nj*8 + t2;
            const size_t iA = ((size_t)(b*CI + cA)*64 + h)*64 + n;
            const size_t iB = ((size_t)(b*CI + cB)*64 + h)*64 + n;
            float2 fA = *(const float2*)(feat + iA);
            float2 fB = *(const float2*)(feat + iB);
            *(float2*)(G + iA) = make_float2(fA.x + gm*acc[mi][nj][0],
                                             fA.y + gm*acc[mi][nj][1]);
            *(float2*)(G + iB) = make_float2(fB.x + gm*acc[mi][nj][2],
                                             fB.y + gm*acc[mi][nj][3]);
        }
    }
}

__global__ void __launch_bounds__(256) oHmma_k(
    const __half* __restrict__ att, const float* __restrict__ vt,
    const float* __restrict__ gamma, float* __restrict__ G)
{
    extern __shared__ __align__(128) char smem[];
    const uint32_t sb = smem_u32(smem);
    const int t = threadIdx.x;
    const int warp = t >> 5, lane = t & 31;
    const int w = blockIdx.x, b = blockIdx.y;

    // Va[c][g] <- fp16(vt[b,c,w,g])
    for (int idx = t; idx < 1024; idx += 256) {
        const int c = idx >> 3, qq = idx & 7;
        float f[8];
        *(float4*)&f[0] = *(const float4*)(vt + ((size_t)(b*CI + c)*64 + w)*64 + qq*8);
        *(float4*)&f[4] = *(const float4*)(vt + ((size_t)(b*CI + c)*64 + w)*64 + qq*8 + 4);
        *(uint4*)(smem + AGG_VA + sw128((uint32_t)(c*128 + qq*16))) = pack8h(f);
    }
    // Aw[hh][g] <- att[b,hh,w][g]
    for (int idx = t; idx < 512; idx += 256) {
        const int hh = idx >> 3, qq = idx & 7;
        uint4 u = *(const uint4*)(att + (size_t)((b*HH + hh)*WW + w)*128 + qq*8);
        *(uint4*)(smem + AGG_AW + sw128((uint32_t)(hh*128 + qq*16))) = u;
    }
    __syncthreads();

    const int m0 = (warp >> 2) * 64;
    const int n0 = (warp & 3) * 16;
    float acc[4][2][4];
    #pragma unroll
    for (int mi = 0; mi < 4; mi++)
        #pragma unroll
        for (int nj = 0; nj < 2; nj++)
            #pragma unroll
            for (int u = 0; u < 4; u++) acc[mi][nj][u] = 0.f;

    const int arow  = lane & 15;
    const int acolb = ((lane >> 4) << 3) * 2;
    const int brow  = (lane & 7) + ((lane >> 4) << 3);
    const int bcolb = (((lane >> 3) & 1) << 3) * 2;

    #pragma unroll
    for (int kk = 0; kk < 4; kk++) {
        const int k0b = kk * 32;
        uint32_t a[4][4], bh[4];
        #pragma unroll
        for (int mi = 0; mi < 4; mi++)
            ldsm4(a[mi], sb + AGG_VA + sw128((uint32_t)((m0 + mi*16 + arow)*128 + k0b + acolb)));
        ldsm4(bh, sb + AGG_AW + sw128((uint32_t)((n0 + brow)*128 + k0b + bcolb)));
        #pragma unroll
        for (int mi = 0; mi < 4; mi++)
            #pragma unroll
            for (int nj = 0; nj < 2; nj++)
                mma16816(acc[mi][nj], a[mi], &bh[nj*2]);
    }

    const float gm = gamma[0];
    const int g  = lane >> 2;
    const int t2 = (lane & 3) * 2;
    #pragma unroll
    for (int mi = 0; mi < 4; mi++) {
        const int cA = m0 + mi*16 + g;
        const int cB = cA + 8;
        #pragma unroll
        for (int nj = 0; nj < 2; nj++) {
            const int n = n0 + nj*8 + t2;   // h index
            const size_t iA0 = ((size_t)(b*CI + cA)*64 + n)*64 + w;
            const size_t iB0 = ((size_t)(b*CI + cB)*64 + n)*64 + w;
            G[iA0]      += gm*acc[mi][nj][0];
            G[iA0 + 64] += gm*acc[mi][nj][1];
            G[iB0]      += gm*acc[mi][nj][2];
            G[iB0 + 64] += gm*acc[mi][nj][3];
        }
    }
}

// =====================================================================
extern "C" void kernel_launch(void* const* d_in, const int* in_sizes, int n_in,
                              void* d_out, int out_size)
{
    (void)in_sizes; (void)n_in; (void)out_size;
    const float* x       = (const float*)d_in[0];
    const float* conva_w = (const float*)d_in[1];
    const float* bn1_g   = (const float*)d_in[2];
    const float* bn1_b   = (const float*)d_in[3];
    const float* bn1_m   = (const float*)d_in[4];
    const float* bn1_v   = (const float*)d_in[5];
    const float* wq      = (const float*)d_in[6];
    const float* bq      = (const float*)d_in[7];
    const float* wk      = (const float*)d_in[8];
    const float* bk      = (const float*)d_in[9];
    const float* wv      = (const float*)d_in[10];
    const float* bv      = (const float*)d_in[11];
    const float* gamma   = (const float*)d_in[12];
    const float* convb_w = (const float*)d_in[13];
    const float* bn2_g   = (const float*)d_in[14];
    const float* bn2_b   = (const float*)d_in[15];
    const float* bn2_m   = (const float*)d_in[16];
    const float* bn2_v   = (const float*)d_in[17];
    const float* bott_w  = (const float*)d_in[18];
    float* out = (float*)d_out;

    float *featA, *featB, *qb, *kb, *ktb, *vb, *vtb;
    __half* attb;
    cudaGetSymbolAddress((void**)&featA, g_featA);
    cudaGetSymbolAddress((void**)&featB, g_featB);
    cudaGetSymbolAddress((void**)&qb,    g_q);
    cudaGetSymbolAddress((void**)&kb,    g_k);
    cudaGetSymbolAddress((void**)&ktb,   g_kt);
    cudaGetSymbolAddress((void**)&vb,    g_v);
    cudaGetSymbolAddress((void**)&vtb,   g_vt);
    cudaGetSymbolAddress((void**)&attb,  g_att4);

    __half *xph, *x2h, *whi, *wqkv;
    cudaGetSymbolAddress((void**)&xph,  g_xph4);
    cudaGetSymbolAddress((void**)&x2h,  g_x2h4);
    cudaGetSymbolAddress((void**)&whi,  g_whi4);
    cudaGetSymbolAddress((void**)&wqkv, g_wqkv4);

    cudaFuncSetAttribute(oWmma_k,   cudaFuncAttributeMaxDynamicSharedMemorySize, AGG_SMEM);
    cudaFuncSetAttribute(oHmma_k,   cudaFuncAttributeMaxDynamicSharedMemorySize, AGG_SMEM);
    cudaFuncSetAttribute(convmma_k, cudaFuncAttributeMaxDynamicSharedMemorySize, SM_TOTAL);

    // ---- conv1 (512 -> 128) + BN1 ----
    wprep_k<<<512, 256>>>(conva_w, CI, CIN, whi);
    pad_k<<<dim3(64, CIN/64, BB), 256>>>(x, CIN, xph, 640, 0);
    zero_border_k<<<1024, 256>>>(xph, 640);
    convmma_k<<<dim3(32, BB), 256, SM_TOTAL>>>(xph, 640, CIN/64, 9,
                                               whi, CIN, CI,
                                               bn1_g, bn1_b, bn1_m, bn1_v,
                                               featA, 0, nullptr, nullptr, nullptr);

    // ---- criss-cross attention x2 (qkv via HMMA 1x1 conv) ----
    wprep_qkv_k<<<128, 256>>>(wq, wk, wv, wqkv);
    zero_border_k<<<1024, 256>>>(x2h, 128);
    float* F = featA;
    float* G = featB;
    for (int it = 0; it < 2; it++) {
        pad_k<<<dim3(64, CI/64, BB), 256>>>(F, CI, x2h, 128, 0);
        convmma_k<<<dim3(32, BB*2), 256, SM_TOTAL>>>(x2h, 128, CI/64, 1,
                                                     wqkv, CI, 256,
                                                     bq, bk, bv, nullptr,
                                                     qb, 3, kb, vb, vtb);
        trans_k<<<BB*CQ, 256>>>(kb, ktb);
        att_k<<<dim3(HH, BB), 256>>>(qb, kb, ktb, attb);
        oWmma_k<<<dim3(HH, BB), 256, AGG_SMEM>>>(attb, vb, F, gamma, G);
        oHmma_k<<<dim3(WW, BB), 256, AGG_SMEM>>>(attb, vtb, gamma, G);
        float* tmp = F; F = G; G = tmp;
    }
    // after 2 iters: F = featA, G = featB

    // ---- convb (128 -> 128) + BN2 ----
    wprep_k<<<576, 256>>>(convb_w, CI, CI, whi);
    pad_k<<<dim3(64, CI/64, BB), 256>>>(F, CI, x2h, 128, 0);
    convmma_k<<<dim3(32, BB), 256, SM_TOTAL>>>(x2h, 128, CI/64, 9,
                                               whi, CI, CI,
                                               bn2_g, bn2_b, bn2_m, bn2_v,
                                               G, 0, nullptr, nullptr, nullptr);

    // ---- bottleneck conv (concat 512+128 -> 512) + ELU ----
    pad_k<<<dim3(64, CI/64, BB), 256>>>(G, CI, xph, 640, CIN);
    wprep_k<<<4096, 256>>>(bott_w, CIN, CIN + CI, whi);
    convmma_k<<<dim3(32, BB*(CIN/128)), 256, SM_TOTAL>>>(xph, 640, (CIN + CI)/64, 9,
                                                         whi, CIN + CI, CIN,
                                                         nullptr, nullptr, nullptr, nullptr,
                                                         out, 1, nullptr, nullptr, nullptr);
}

// round 13
// speedup vs baseline: 1.1344x; 1.1344x over previous
#include <cuda_runtime.h>
#include <cuda_fp16.h>
#include <math.h>
#include <stdint.h>

#define BB 8
#define HH 64
#define WW 64
#define HWSZ 4096
#define CI 128
#define CQ 16
#define CIN 512

// ---------------- scratch buffers (static device allocations) ----------------
__device__ float g_featA[BB*CI*HWSZ];
__device__ float g_featB[BB*CI*HWSZ];
__device__ float g_q [BB*CQ*HWSZ];
__device__ float g_k [BB*CQ*HWSZ];
__device__ float g_kt[BB*CQ*HWSZ];
__device__ float g_v [BB*CI*HWSZ];
__device__ float g_vt[BB*CI*HWSZ];
__device__ uint4 g_att4[(8ULL*HH*WW*128*2)/16];   // fp16 att [b,h,w][128]

// padded NHWC fp16 feature maps (16B aligned via uint4)
#define XP640_ELEMS (8ULL*66*66*640)
#define XP128_ELEMS (8ULL*66*66*128)
#define WSP_ELEMS   (9ULL*512*640)
__device__ uint4 g_xph4[XP640_ELEMS/8];
__device__ uint4 g_x2h4[XP128_ELEMS/8];
__device__ uint4 g_whi4[WSP_ELEMS/8];
__device__ uint4 g_wqkv4[(256*128)/8];   // packed q|k|v|pad weights, fp16

// =====================================================================
// PTX helpers (compute_103-safe: mma.sync / ldmatrix / cp.async only)
// =====================================================================
__device__ __forceinline__ uint32_t smem_u32(const void* p) {
    uint32_t a;
    asm("{ .reg .u64 t; cvta.to.shared.u64 t, %1; cvt.u32.u64 %0, t; }" : "=r"(a) : "l"(p));
    return a;
}
__device__ __forceinline__ void cpa16(uint32_t dst, const void* src) {
    asm volatile("cp.async.cg.shared.global [%0], [%1], 16;" :: "r"(dst), "l"(src) : "memory");
}
__device__ __forceinline__ void cpa_commit() {
    asm volatile("cp.async.commit_group;" ::: "memory");
}
__device__ __forceinline__ void cpa_wait1() {
    asm volatile("cp.async.wait_group 1;" ::: "memory");
}
__device__ __forceinline__ void cpa_wait0() {
    asm volatile("cp.async.wait_group 0;" ::: "memory");
}
__device__ __forceinline__ void ldsm4(uint32_t* r, uint32_t addr) {
    asm volatile("ldmatrix.sync.aligned.m8n8.x4.shared.b16 {%0,%1,%2,%3}, [%4];"
                 : "=r"(r[0]), "=r"(r[1]), "=r"(r[2]), "=r"(r[3]) : "r"(addr));
}
__device__ __forceinline__ void mma16816(float* c, const uint32_t* a, const uint32_t* b) {
    asm volatile(
        "mma.sync.aligned.m16n8k16.row.col.f32.f16.f16.f32 "
        "{%0,%1,%2,%3}, {%4,%5,%6,%7}, {%8,%9}, {%0,%1,%2,%3};"
        : "+f"(c[0]), "+f"(c[1]), "+f"(c[2]), "+f"(c[3])
        : "r"(a[0]), "r"(a[1]), "r"(a[2]), "r"(a[3]), "r"(b[0]), "r"(b[1]));
}
__device__ __forceinline__ uint32_t sw128(uint32_t off) {
    return off ^ ((off >> 3) & 0x70);
}
__device__ __forceinline__ uint4 pack8h(const float* f) {
    __half2 h0 = __floats2half2_rn(f[0], f[1]);
    __half2 h1 = __floats2half2_rn(f[2], f[3]);
    __half2 h2 = __floats2half2_rn(f[4], f[5]);
    __half2 h3 = __floats2half2_rn(f[6], f[7]);
    uint4 u;
    u.x = *(uint32_t*)&h0; u.y = *(uint32_t*)&h1;
    u.z = *(uint32_t*)&h2; u.w = *(uint32_t*)&h3;
    return u;
}

// =====================================================================
// prep: NCHW fp32 -> padded NHWC fp16 (interior only)
// =====================================================================
__global__ void __launch_bounds__(256) pad_k(
    const float* __restrict__ src, int C,
    __half* __restrict__ dh, int pitch, int colofs)
{
    __shared__ float s[64][65];
    const int y = blockIdx.x, cbase = blockIdx.y * 64, b = blockIdx.z;
    const int t = threadIdx.x;
    for (int idx = t; idx < 4096; idx += 256) {
        int icl = idx >> 6, x = idx & 63;
        s[icl][x] = src[((size_t)(b*C + cbase + icl)*64 + y)*64 + x];
    }
    __syncthreads();
    for (int idx = t; idx < 4096; idx += 256) {
        int x = idx >> 6, icl = idx & 63;
        size_t o = ((size_t)(b*66 + y + 1)*66 + (x + 1))*pitch + colofs + cbase + icl;
        dh[o] = __float2half_rn(s[icl][x]);
    }
}

__global__ void __launch_bounds__(256) zero_border_k(
    __half* __restrict__ dh, int pitch)
{
    const int total = 8 * 260 * pitch;
    for (int idx = blockIdx.x*256 + threadIdx.x; idx < total; idx += gridDim.x*256) {
        int ic = idx % pitch;
        int r  = idx / pitch;
        int b  = r / 260;
        int pos = r % 260;
        int yy, xx;
        if      (pos < 66)  { yy = 0;  xx = pos; }
        else if (pos < 132) { yy = 65; xx = pos - 66; }
        else if (pos < 196) { yy = pos - 132 + 1; xx = 0; }
        else                { yy = pos - 196 + 1; xx = 65; }
        dh[((size_t)(b*66 + yy)*66 + xx)*pitch + ic] = __float2half_rn(0.f);
    }
}

// weights: w[oc][ic][3][3] fp32 -> Wh [tap][oc][ic] fp16
__global__ void __launch_bounds__(256) wprep_k(
    const float* __restrict__ w, int Cout, int Ctot,
    __half* __restrict__ wh)
{
    const int total = Cout * Ctot * 9;
    for (int idx = blockIdx.x*256 + threadIdx.x; idx < total; idx += gridDim.x*256) {
        int ic  = idx % Ctot;
        int r   = idx / Ctot;
        int oc  = r % Cout;
        int tap = r / Cout;
        wh[(size_t)(tap*Cout + oc)*Ctot + ic] =
            __float2half_rn(w[(size_t)(oc*Ctot + ic)*9 + tap]);
    }
}

// packed qkv weights: [256 oc][128 ic] fp16 = q(16) | k(16) | v(128) | zeros(96)
__global__ void __launch_bounds__(256) wprep_qkv_k(
    const float* __restrict__ wq, const float* __restrict__ wk,
    const float* __restrict__ wv, __half* __restrict__ wh)
{
    const int total = 256 * 128;
    for (int idx = blockIdx.x*256 + threadIdx.x; idx < total; idx += gridDim.x*256) {
        int oc = idx >> 7, ic = idx & 127;
        float v = 0.f;
        if      (oc < 16)  v = wq[oc*128 + ic];
        else if (oc < 32)  v = wk[(oc-16)*128 + ic];
        else if (oc < 160) v = wv[(oc-32)*128 + ic];
        wh[idx] = __float2half_rn(v);
    }
}

// =====================================================================
// HMMA implicit-GEMM conv (frozen R7/R11 structure).
// modes: 0 = BN, 1 = ELU(512), 3 = qkv scatter (q, k, v + vt)
// =====================================================================
#define TILE_B (128*128)
#define OFF_A  0
#define OFF_B  TILE_B
#define STAGE_B (2*TILE_B)
#define SM_TOTAL (3*STAGE_B)

__global__ void __launch_bounds__(256, 2) convmma_k(
    const __half* __restrict__ Xh,
    int pitch, int chunks, int ntap,
    const __half* __restrict__ Wh,
    int Ctot, int Cout,
    const float* __restrict__ p0, const float* __restrict__ p1,
    const float* __restrict__ p2, const float* __restrict__ p3,
    float* __restrict__ out, int mode,
    float* __restrict__ out2, float* __restrict__ out3,
    float* __restrict__ out3t)
{
    extern __shared__ __align__(128) char smem[];
    const uint32_t sb = smem_u32(smem);
    const int t = threadIdx.x;
    const int warp = t >> 5, lane = t & 31;
    const int nog = Cout >> 7;
    const int ocg = blockIdx.y % nog;
    const int b   = blockIdx.y / nog;
    const int y0  = blockIdx.x * 2;
    const int ocb = ocg * 128;

    const int q8 = t & 7;
    const int r0 = t >> 3;

    const int T = chunks * ntap;

    auto issue_tile = [&](int i) {
        const int c   = i / ntap;
        const int tap = i - c*ntap;
        const int dy  = (ntap == 1) ? 1 : tap / 3;
        const int dx  = (ntap == 1) ? 1 : tap - (tap/3)*3;
        const int ic0 = c * 64;
        const uint32_t base = sb + (uint32_t)(i % 3) * STAGE_B;
        #pragma unroll
        for (int p = 0; p < 4; p++) {
            const int m = r0 + 32*p;
            const uint32_t so = sw128((uint32_t)(m*128 + q8*16));
            cpa16(base + OFF_A + so,
                  Wh + (size_t)(tap*Cout + ocb + m)*Ctot + ic0 + q8*8);
            const int yl = m >> 6, x = m & 63;
            cpa16(base + OFF_B + so,
                  Xh + ((size_t)(b*66 + y0 + yl + dy)*66 + (x + dx))*pitch + ic0 + q8*8);
        }
        cpa_commit();
    };

    const int m0 = (warp >> 2) * 64;
    const int n0 = (warp & 3) * 32;
    float acc[4][4][4];
    #pragma unroll
    for (int mi = 0; mi < 4; mi++)
        #pragma unroll
        for (int nj = 0; nj < 4; nj++)
            #pragma unroll
            for (int u = 0; u < 4; u++) acc[mi][nj][u] = 0.f;

    const int arow  = lane & 15;
    const int acolb = ((lane >> 4) << 3) * 2;
    const int brow  = (lane & 7) + ((lane >> 4) << 3);
    const int bcolb = (((lane >> 3) & 1) << 3) * 2;

    issue_tile(0);
    if (T > 1) issue_tile(1);

    for (int i = 0; i < T; i++) {
        if (i + 1 < T) cpa_wait1();
        else           cpa_wait0();
        __syncthreads();
        if (i + 2 < T) issue_tile(i + 2);

        const uint32_t base = sb + (uint32_t)(i % 3) * STAGE_B;
        const uint32_t sA = base + OFF_A;
        const uint32_t sB = base + OFF_B;

        #pragma unroll
        for (int kk = 0; kk < 4; kk++) {
            const int k0b = kk * 32;
            uint32_t a[4][4], bh[2][4];
            #pragma unroll
            for (int mi = 0; mi < 4; mi++) {
                const uint32_t ro = sw128((uint32_t)((m0 + mi*16 + arow) * 128 + k0b + acolb));
                ldsm4(a[mi], sA + ro);
            }
            #pragma unroll
            for (int ni = 0; ni < 2; ni++) {
                const uint32_t ro = sw128((uint32_t)((n0 + ni*16 + brow) * 128 + k0b + bcolb));
                ldsm4(bh[ni], sB + ro);
            }
            #pragma unroll
            for (int mi = 0; mi < 4; mi++)
                #pragma unroll
                for (int nj = 0; nj < 4; nj++)
                    mma16816(acc[mi][nj], a[mi], &bh[nj >> 1][(nj & 1) * 2]);
        }
    }

    // ---- epilogue ----
    const int g  = lane >> 2;
    const int t2 = (lane & 3) * 2;
    #pragma unroll
    for (int mi = 0; mi < 4; mi++) {
        const int ocA = ocb + m0 + mi*16 + g;
        const int ocB = ocA + 8;
        float scA = 1.f, biA = 0.f, scB = 1.f, biB = 0.f;
        if (mode == 0) {
            scA = p0[ocA] * rsqrtf(p3[ocA] + 1e-5f);
            biA = p1[ocA] - p2[ocA] * scA;
            scB = p0[ocB] * rsqrtf(p3[ocB] + 1e-5f);
            biB = p1[ocB] - p2[ocB] * scB;
        }
        #pragma unroll
        for (int nj = 0; nj < 4; nj++) {
            const int n  = n0 + nj*8 + t2;
            const int yl = n >> 6, x = n & 63;
            const int py = y0 + yl;
            float v0 = acc[mi][nj][0], v1 = acc[mi][nj][1];
            float v2 = acc[mi][nj][2], v3 = acc[mi][nj][3];
            if (mode == 3) {
                #pragma unroll
                for (int h = 0; h < 2; h++) {
                    const int oc = h ? ocB : ocA;
                    float u0 = h ? v2 : v0;
                    float u1 = h ? v3 : v1;
                    if (oc < 16) {
                        float bi = p0[oc];
                        *(float2*)&out[((size_t)(b*CQ + oc)*64 + py)*64 + x] =
                            make_float2(u0 + bi, u1 + bi);
                    } else if (oc < 32) {
                        float bi = p1[oc - 16];
                        *(float2*)&out2[((size_t)(b*CQ + oc - 16)*64 + py)*64 + x] =
                            make_float2(u0 + bi, u1 + bi);
                    } else if (oc < 160) {
                        const int c = oc - 32;
                        float bi = p2[c];
                        u0 += bi; u1 += bi;
                        *(float2*)&out3[((size_t)(b*CI + c)*64 + py)*64 + x] =
                            make_float2(u0, u1);
                        out3t[((size_t)(b*CI + c)*64 + x    )*64 + py] = u0;
                        out3t[((size_t)(b*CI + c)*64 + x + 1)*64 + py] = u1;
                    }
                }
                continue;
            }
            if (mode == 0) {
                v0 = v0*scA + biA; v1 = v1*scA + biA;
                v2 = v2*scB + biB; v3 = v3*scB + biB;
            } else {
                if (v0 <= 0.f) v0 = 512.0f * expm1f(v0);
                if (v1 <= 0.f) v1 = 512.0f * expm1f(v1);
                if (v2 <= 0.f) v2 = 512.0f * expm1f(v2);
                if (v3 <= 0.f) v3 = 512.0f * expm1f(v3);
            }
            *(float2*)&out[((size_t)(b*Cout + ocA)*64 + py)*64 + x] = make_float2(v0, v1);
            *(float2*)&out[((size_t)(b*Cout + ocB)*64 + py)*64 + x] = make_float2(v2, v3);
        }
    }
}

// =====================================================================
// attention: trans_k (kt), att_k (logits+softmax -> fp16 att)
// =====================================================================
__global__ void __launch_bounds__(256) trans_k(const float* __restrict__ in,
                                               float* __restrict__ out)
{
    __shared__ float s[64][65];
    const float* src = in  + (size_t)blockIdx.x * 4096;
    float*       dst = out + (size_t)blockIdx.x * 4096;
    for (int idx = threadIdx.x; idx < 4096; idx += 256)
        s[idx >> 6][idx & 63] = src[idx];
    __syncthreads();
    for (int idx = threadIdx.x; idx < 4096; idx += 256)
        dst[idx] = s[idx & 63][idx >> 6];
}

__global__ void __launch_bounds__(256) att_k(
    const float* __restrict__ q, const float* __restrict__ k,
    const float* __restrict__ kt, __half* __restrict__ att)
{
    __shared__ float qs[16*64];
    __shared__ float ks[16*64];
    __shared__ float E[64*128];

    const int t = threadIdx.x;
    const int h = blockIdx.x, b = blockIdx.y;

    for (int idx = t; idx < 1024; idx += 256) {
        int c = idx >> 6, w = idx & 63;
        qs[idx] = q[((b*CQ + c)*HH + h)*WW + w];
        ks[idx] = k[((b*CQ + c)*HH + h)*WW + w];
    }
    __syncthreads();

    for (int idx = t; idx < 2048; idx += 256) {
        const int w  = idx >> 5;
        const int j4 = idx & 31;
        float4 e = make_float4(0.f, 0.f, 0.f, 0.f);
        if (j4 < 16) {
            for (int c = 0; c < 16; c++) {
                float qq = qs[c*64 + w];
                float4 kv = ((const float4*)kt)[((b*CQ + c)*WW + w)*16 + j4];
                e.x += qq * kv.x; e.y += qq * kv.y; e.z += qq * kv.z; e.w += qq * kv.w;
            }
            if ((h >> 2) == j4) ((float*)&e)[h & 3] = -INFINITY;
        } else {
            for (int c = 0; c < 16; c++) {
                float qq = qs[c*64 + w];
                float4 kv = ((const float4*)ks)[c*16 + (j4 - 16)];
                e.x += qq * kv.x; e.y += qq * kv.y; e.z += qq * kv.z; e.w += qq * kv.w;
            }
        }
        ((float4*)E)[w*32 + j4] = e;
    }
    __syncthreads();

    const int lane = t & 31, wid = t >> 5;
    for (int r = 0; r < 8; r++) {
        const int w = wid*8 + r;
        float v0 = E[w*128 + lane],      v1 = E[w*128 + lane + 32];
        float v2 = E[w*128 + lane + 64], v3 = E[w*128 + lane + 96];
        float m = fmaxf(fmaxf(v0, v1), fmaxf(v2, v3));
        #pragma unroll
        for (int s = 16; s; s >>= 1) m = fmaxf(m, __shfl_xor_sync(0xffffffffu, m, s));
        float e0 = expf(v0 - m), e1 = expf(v1 - m), e2 = expf(v2 - m), e3 = expf(v3 - m);
        float sum = e0 + e1 + e2 + e3;
        #pragma unroll
        for (int s = 16; s; s >>= 1) sum += __shfl_xor_sync(0xffffffffu, sum, s);
        float inv = 1.f / sum;
        __half* dst = att + (size_t)((b*HH + h)*WW + w)*128;
        dst[lane]      = __float2half_rn(e0*inv);
        dst[lane + 32] = __float2half_rn(e1*inv);
        dst[lane + 64] = __float2half_rn(e2*inv);
        dst[lane + 96] = __float2half_rn(e3*inv);
    }
}

// =====================================================================
// oH_k (FFMA, R11 structure, fp16 att reads): per (b,w):
//   G[c][h] = sum_g vt[c,g] * aH[h,g]   (raw oH, store-only scatter)
// =====================================================================
#define OHW_SMEM ((64*69 + 64*132)*4)

__global__ void __launch_bounds__(256) oH_k(
    const __half* __restrict__ att, const float* __restrict__ vt,
    float* __restrict__ outb)
{
    extern __shared__ __align__(16) float sm[];
    float* As = sm;                 // [g][69]
    float* Vs = sm + 64*69;         // [g][132]

    const int t = threadIdx.x;
    const int w = blockIdx.x, b = blockIdx.y;

    for (int idx = t; idx < 4096; idx += 256) {
        int hh = idx >> 6, g = idx & 63;
        As[g*69 + hh] = __half2float(att[(size_t)((b*HH + hh)*WW + w)*128 + g]);
    }
    for (int idx = t; idx < 8192; idx += 256) {
        int c = idx >> 6, g = idx & 63;
        Vs[g*132 + c] = vt[((b*CI + c)*WW + w)*HH + g];
    }
    __syncthreads();

    const int c0 = (t & 31) * 4;
    const int h0 = (t >> 5) * 8;
    float acc[8][4];
    #pragma unroll
    for (int i = 0; i < 8; i++)
        #pragma unroll
        for (int j = 0; j < 4; j++) acc[i][j] = 0.f;

    for (int g = 0; g < 64; g++) {
        float4 v4 = *(const float4*)&Vs[g*132 + c0];
        #pragma unroll
        for (int hi = 0; hi < 8; hi++) {
            float av = As[g*69 + h0 + hi];
            acc[hi][0] += av * v4.x; acc[hi][1] += av * v4.y;
            acc[hi][2] += av * v4.z; acc[hi][3] += av * v4.w;
        }
    }
    #pragma unroll
    for (int hi = 0; hi < 8; hi++)
        #pragma unroll
        for (int ci = 0; ci < 4; ci++)
            outb[((b*CI + c0 + ci)*HH + h0 + hi)*WW + w] = acc[hi][ci];
}

// =====================================================================
// oWmma_k: per (b,h): C[c][w] = sum_wp v[c,wp]*aW[w,wp] via HMMA;
//          G = feat + gamma*(G_prev(oH) + C)   (coalesced float2 RMW)
// =====================================================================
#define AGG_VA   0
#define AGG_AW   16384
#define AGG_SMEM (16384 + 8192)

__global__ void __launch_bounds__(256) oWmma_k(
    const __half* __restrict__ att, const float* __restrict__ v,
    const float* __restrict__ feat, const float* __restrict__ gamma,
    float* __restrict__ G)
{
    extern __shared__ __align__(128) char smem[];
    const uint32_t sb = smem_u32(smem);
    const int t = threadIdx.x;
    const int warp = t >> 5, lane = t & 31;
    const int h = blockIdx.x, b = blockIdx.y;

    // Va[c][wp] <- fp16(v[b,c,h,wp])
    for (int idx = t; idx < 1024; idx += 256) {
        const int c = idx >> 3, qq = idx & 7;
        float f[8];
        *(float4*)&f[0] = *(const float4*)(v + ((size_t)(b*CI + c)*64 + h)*64 + qq*8);
        *(float4*)&f[4] = *(const float4*)(v + ((size_t)(b*CI + c)*64 + h)*64 + qq*8 + 4);
        *(uint4*)(smem + AGG_VA + sw128((uint32_t)(c*128 + qq*16))) = pack8h(f);
    }
    // Aw[w][wp] <- att[b,h,w][64+wp]
    for (int idx = t; idx < 512; idx += 256) {
        const int w = idx >> 3, qq = idx & 7;
        uint4 u = *(const uint4*)(att + (size_t)((b*HH + h)*WW + w)*128 + 64 + qq*8);
        *(uint4*)(smem + AGG_AW + sw128((uint32_t)(w*128 + qq*16))) = u;
    }
    __syncthreads();

    const int m0 = (warp >> 2) * 64;
    const int n0 = (warp & 3) * 16;
    float acc[4][2][4];
    #pragma unroll
    for (int mi = 0; mi < 4; mi++)
        #pragma unroll
        for (int nj = 0; nj < 2; nj++)
            #pragma unroll
            for (int u = 0; u < 4; u++) acc[mi][nj][u] = 0.f;

    const int arow  = lane & 15;
    const int acolb = ((lane >> 4) << 3) * 2;
    const int brow  = (lane & 7) + ((lane >> 4) << 3);
    const int bcolb = (((lane >> 3) & 1) << 3) * 2;

    #pragma unroll
    for (int kk = 0; kk < 4; kk++) {
        const int k0b = kk * 32;
        uint32_t a[4][4], bh[4];
        #pragma unroll
        for (int mi = 0; mi < 4; mi++)
            ldsm4(a[mi], sb + AGG_VA + sw128((uint32_t)((m0 + mi*16 + arow)*128 + k0b + acolb)));
        ldsm4(bh, sb + AGG_AW + sw128((uint32_t)((n0 + brow)*128 + k0b + bcolb)));
        #pragma unroll
        for (int mi = 0; mi < 4; mi++)
            #pragma unroll
            for (int nj = 0; nj < 2; nj++)
                mma16816(acc[mi][nj], a[mi], &bh[nj*2]);
    }

    const float gm = gamma[0];
    const int g  = lane >> 2;
    const int t2 = (lane & 3) * 2;
    #pragma unroll
    for (int mi = 0; mi < 4; mi++) {
        const int cA = m0 + mi*16 + g;
        const int cB = cA + 8;
        #pragma unroll
        for (int nj = 0; nj < 2; nj++) {
            const int n = n0 + nj*8 + t2;
            const size_t iA = ((size_t)(b*CI + cA)*64 + h)*64 + n;
            const size_t iB = ((size_t)(b*CI + cB)*64 + h)*64 + n;
            float2 fA = *(const float2*)(feat + iA);
            float2 fB = *(const float2*)(feat + iB);
            float2 gA = *(const float2*)(G + iA);     // raw oH from oH_k
            float2 gB = *(const float2*)(G + iB);
            *(float2*)(G + iA) = make_float2(fA.x + gm*(gA.x + acc[mi][nj][0]),
                                             fA.y + gm*(gA.y + acc[mi][nj][1]));
            *(float2*)(G + iB) = make_float2(fB.x + gm*(gB.x + acc[mi][nj][2]),
                                             fB.y + gm*(gB.y + acc[mi][nj][3]));
        }
    }
}

// =====================================================================
extern "C" void kernel_launch(void* const* d_in, const int* in_sizes, int n_in,
                              void* d_out, int out_size)
{
    (void)in_sizes; (void)n_in; (void)out_size;
    const float* x       = (const float*)d_in[0];
    const float* conva_w = (const float*)d_in[1];
    const float* bn1_g   = (const float*)d_in[2];
    const float* bn1_b   = (const float*)d_in[3];
    const float* bn1_m   = (const float*)d_in[4];
    const float* bn1_v   = (const float*)d_in[5];
    const float* wq      = (const float*)d_in[6];
    const float* bq      = (const float*)d_in[7];
    const float* wk      = (const float*)d_in[8];
    const float* bk      = (const float*)d_in[9];
    const float* wv      = (const float*)d_in[10];
    const float* bv      = (const float*)d_in[11];
    const float* gamma   = (const float*)d_in[12];
    const float* convb_w = (const float*)d_in[13];
    const float* bn2_g   = (const float*)d_in[14];
    const float* bn2_b   = (const float*)d_in[15];
    const float* bn2_m   = (const float*)d_in[16];
    const float* bn2_v   = (const float*)d_in[17];
    const float* bott_w  = (const float*)d_in[18];
    float* out = (float*)d_out;

    float *featA, *featB, *qb, *kb, *ktb, *vb, *vtb;
    __half* attb;
    cudaGetSymbolAddress((void**)&featA, g_featA);
    cudaGetSymbolAddress((void**)&featB, g_featB);
    cudaGetSymbolAddress((void**)&qb,    g_q);
    cudaGetSymbolAddress((void**)&kb,    g_k);
    cudaGetSymbolAddress((void**)&ktb,   g_kt);
    cudaGetSymbolAddress((void**)&vb,    g_v);
    cudaGetSymbolAddress((void**)&vtb,   g_vt);
    cudaGetSymbolAddress((void**)&attb,  g_att4);

    __half *xph, *x2h, *whi, *wqkv;
    cudaGetSymbolAddress((void**)&xph,  g_xph4);
    cudaGetSymbolAddress((void**)&x2h,  g_x2h4);
    cudaGetSymbolAddress((void**)&whi,  g_whi4);
    cudaGetSymbolAddress((void**)&wqkv, g_wqkv4);

    cudaFuncSetAttribute(oH_k,      cudaFuncAttributeMaxDynamicSharedMemorySize, OHW_SMEM);
    cudaFuncSetAttribute(oWmma_k,   cudaFuncAttributeMaxDynamicSharedMemorySize, AGG_SMEM);
    cudaFuncSetAttribute(convmma_k, cudaFuncAttributeMaxDynamicSharedMemorySize, SM_TOTAL);

    // ---- conv1 (512 -> 128) + BN1 ----
    wprep_k<<<512, 256>>>(conva_w, CI, CIN, whi);
    pad_k<<<dim3(64, CIN/64, BB), 256>>>(x, CIN, xph, 640, 0);
    zero_border_k<<<1024, 256>>>(xph, 640);
    convmma_k<<<dim3(32, BB), 256, SM_TOTAL>>>(xph, 640, CIN/64, 9,
                                               whi, CIN, CI,
                                               bn1_g, bn1_b, bn1_m, bn1_v,
                                               featA, 0, nullptr, nullptr, nullptr);

    // ---- criss-cross attention x2 (qkv via HMMA 1x1 conv) ----
    wprep_qkv_k<<<128, 256>>>(wq, wk, wv, wqkv);
    zero_border_k<<<1024, 256>>>(x2h, 128);
    float* F = featA;
    float* G = featB;
    for (int it = 0; it < 2; it++) {
        pad_k<<<dim3(64, CI/64, BB), 256>>>(F, CI, x2h, 128, 0);
        convmma_k<<<dim3(32, BB*2), 256, SM_TOTAL>>>(x2h, 128, CI/64, 1,
                                                     wqkv, CI, 256,
                                                     bq, bk, bv, nullptr,
                                                     qb, 3, kb, vb, vtb);
        trans_k<<<BB*CQ, 256>>>(kb, ktb);
        att_k<<<dim3(HH, BB), 256>>>(qb, kb, ktb, attb);
        oH_k<<<dim3(WW, BB), 256, OHW_SMEM>>>(attb, vtb, G);
        oWmma_k<<<dim3(HH, BB), 256, AGG_SMEM>>>(attb, vb, F, gamma, G);
        float* tmp = F; F = G; G = tmp;
    }
    // after 2 iters: F = featA, G = featB

    // ---- convb (128 -> 128) + BN2 ----
    wprep_k<<<576, 256>>>(convb_w, CI, CI, whi);
    pad_k<<<dim3(64, CI/64, BB), 256>>>(F, CI, x2h, 128, 0);
    convmma_k<<<dim3(32, BB), 256, SM_TOTAL>>>(x2h, 128, CI/64, 9,
                                               whi, CI, CI,
                                               bn2_g, bn2_b, bn2_m, bn2_v,
                                               G, 0, nullptr, nullptr, nullptr);

    // ---- bottleneck conv (concat 512+128 -> 512) + ELU ----
    pad_k<<<dim3(64, CI/64, BB), 256>>>(G, CI, xph, 640, CIN);
    wprep_k<<<4096, 256>>>(bott_w, CIN, CIN + CI, whi);
    convmma_k<<<dim3(32, BB*(CIN/128)), 256, SM_TOTAL>>>(xph, 640, (CIN + CI)/64, 9,
                                                         whi, CIN + CI, CIN,
                                                         nullptr, nullptr, nullptr, nullptr,
                                                         out, 1, nullptr, nullptr, nullptr);
}

// round 14
// speedup vs baseline: 1.1598x; 1.0224x over previous
#include <cuda_runtime.h>
#include <cuda_fp16.h>
#include <math.h>
#include <stdint.h>

#define BB 8
#define HH 64
#define WW 64
#define HWSZ 4096
#define CI 128
#define CQ 16
#define CIN 512

// ---------------- scratch buffers (static device allocations) ----------------
__device__ float g_featA[BB*CI*HWSZ];
__device__ float g_featB[BB*CI*HWSZ];
__device__ float g_q [BB*CQ*HWSZ];
__device__ float g_k [BB*CQ*HWSZ];
__device__ float g_kt[BB*CQ*HWSZ];
__device__ float g_v [BB*CI*HWSZ];
__device__ float g_vt[BB*CI*HWSZ];
__device__ uint4 g_att4[(8ULL*HH*WW*128*2)/16];   // fp16 att [b,h,w][128]

// padded NHWC fp16 feature maps (16B aligned via uint4)
#define XP640_ELEMS (8ULL*66*66*640)
#define XP128_ELEMS (8ULL*66*66*128)
#define WSP_ELEMS   (9ULL*512*640)
__device__ uint4 g_xph4[XP640_ELEMS/8];
__device__ uint4 g_x2h4[XP128_ELEMS/8];
__device__ uint4 g_whi4[WSP_ELEMS/8];
__device__ uint4 g_wqkv4[(256*128)/8];   // packed q|k|v|pad weights, fp16

// =====================================================================
// PTX helpers (compute_103-safe: mma.sync / ldmatrix / cp.async only)
// =====================================================================
__device__ __forceinline__ uint32_t smem_u32(const void* p) {
    uint32_t a;
    asm("{ .reg .u64 t; cvta.to.shared.u64 t, %1; cvt.u32.u64 %0, t; }" : "=r"(a) : "l"(p));
    return a;
}
__device__ __forceinline__ void cpa16(uint32_t dst, const void* src) {
    asm volatile("cp.async.cg.shared.global [%0], [%1], 16;" :: "r"(dst), "l"(src) : "memory");
}
__device__ __forceinline__ void cpa_commit() {
    asm volatile("cp.async.commit_group;" ::: "memory");
}
__device__ __forceinline__ void cpa_wait1() {
    asm volatile("cp.async.wait_group 1;" ::: "memory");
}
__device__ __forceinline__ void cpa_wait0() {
    asm volatile("cp.async.wait_group 0;" ::: "memory");
}
__device__ __forceinline__ void ldsm4(uint32_t* r, uint32_t addr) {
    asm volatile("ldmatrix.sync.aligned.m8n8.x4.shared.b16 {%0,%1,%2,%3}, [%4];"
                 : "=r"(r[0]), "=r"(r[1]), "=r"(r[2]), "=r"(r[3]) : "r"(addr));
}
__device__ __forceinline__ void mma16816(float* c, const uint32_t* a, const uint32_t* b) {
    asm volatile(
        "mma.sync.aligned.m16n8k16.row.col.f32.f16.f16.f32 "
        "{%0,%1,%2,%3}, {%4,%5,%6,%7}, {%8,%9}, {%0,%1,%2,%3};"
        : "+f"(c[0]), "+f"(c[1]), "+f"(c[2]), "+f"(c[3])
        : "r"(a[0]), "r"(a[1]), "r"(a[2]), "r"(a[3]), "r"(b[0]), "r"(b[1]));
}
__device__ __forceinline__ uint32_t sw128(uint32_t off) {
    return off ^ ((off >> 3) & 0x70);
}
__device__ __forceinline__ uint4 pack8h(const float* f) {
    __half2 h0 = __floats2half2_rn(f[0], f[1]);
    __half2 h1 = __floats2half2_rn(f[2], f[3]);
    __half2 h2 = __floats2half2_rn(f[4], f[5]);
    __half2 h3 = __floats2half2_rn(f[6], f[7]);
    uint4 u;
    u.x = *(uint32_t*)&h0; u.y = *(uint32_t*)&h1;
    u.z = *(uint32_t*)&h2; u.w = *(uint32_t*)&h3;
    return u;
}

// =====================================================================
// prep: NCHW fp32 -> padded NHWC fp16 (interior only)
// =====================================================================
__global__ void __launch_bounds__(256) pad_k(
    const float* __restrict__ src, int C,
    __half* __restrict__ dh, int pitch, int colofs)
{
    __shared__ float s[64][65];
    const int y = blockIdx.x, cbase = blockIdx.y * 64, b = blockIdx.z;
    const int t = threadIdx.x;
    for (int idx = t; idx < 4096; idx += 256) {
        int icl = idx >> 6, x = idx & 63;
        s[icl][x] = src[((size_t)(b*C + cbase + icl)*64 + y)*64 + x];
    }
    __syncthreads();
    for (int idx = t; idx < 4096; idx += 256) {
        int x = idx >> 6, icl = idx & 63;
        size_t o = ((size_t)(b*66 + y + 1)*66 + (x + 1))*pitch + colofs + cbase + icl;
        dh[o] = __float2half_rn(s[icl][x]);
    }
}

__global__ void __launch_bounds__(256) zero_border_k(
    __half* __restrict__ dh, int pitch)
{
    const int total = 8 * 260 * pitch;
    for (int idx = blockIdx.x*256 + threadIdx.x; idx < total; idx += gridDim.x*256) {
        int ic = idx % pitch;
        int r  = idx / pitch;
        int b  = r / 260;
        int pos = r % 260;
        int yy, xx;
        if      (pos < 66)  { yy = 0;  xx = pos; }
        else if (pos < 132) { yy = 65; xx = pos - 66; }
        else if (pos < 196) { yy = pos - 132 + 1; xx = 0; }
        else                { yy = pos - 196 + 1; xx = 65; }
        dh[((size_t)(b*66 + yy)*66 + xx)*pitch + ic] = __float2half_rn(0.f);
    }
}

// weights: w[oc][ic][3][3] fp32 -> Wh [tap][oc][ic] fp16
__global__ void __launch_bounds__(256) wprep_k(
    const float* __restrict__ w, int Cout, int Ctot,
    __half* __restrict__ wh)
{
    const int total = Cout * Ctot * 9;
    for (int idx = blockIdx.x*256 + threadIdx.x; idx < total; idx += gridDim.x*256) {
        int ic  = idx % Ctot;
        int r   = idx / Ctot;
        int oc  = r % Cout;
        int tap = r / Cout;
        wh[(size_t)(tap*Cout + oc)*Ctot + ic] =
            __float2half_rn(w[(size_t)(oc*Ctot + ic)*9 + tap]);
    }
}

// packed qkv weights: [256 oc][128 ic] fp16 = q(16) | k(16) | v(128) | zeros(96)
__global__ void __launch_bounds__(256) wprep_qkv_k(
    const float* __restrict__ wq, const float* __restrict__ wk,
    const float* __restrict__ wv, __half* __restrict__ wh)
{
    const int total = 256 * 128;
    for (int idx = blockIdx.x*256 + threadIdx.x; idx < total; idx += gridDim.x*256) {
        int oc = idx >> 7, ic = idx & 127;
        float v = 0.f;
        if      (oc < 16)  v = wq[oc*128 + ic];
        else if (oc < 32)  v = wk[(oc-16)*128 + ic];
        else if (oc < 160) v = wv[(oc-32)*128 + ic];
        wh[idx] = __float2half_rn(v);
    }
}

// =====================================================================
// HMMA implicit-GEMM conv (frozen R7/R11 structure).
// modes: 0 = BN, 1 = ELU(512), 3 = qkv scatter (q, k + kt, v + vt)
// =====================================================================
#define TILE_B (128*128)
#define OFF_A  0
#define OFF_B  TILE_B
#define STAGE_B (2*TILE_B)
#define SM_TOTAL (3*STAGE_B)

__global__ void __launch_bounds__(256, 2) convmma_k(
    const __half* __restrict__ Xh,
    int pitch, int chunks, int ntap,
    const __half* __restrict__ Wh,
    int Ctot, int Cout,
    const float* __restrict__ p0, const float* __restrict__ p1,
    const float* __restrict__ p2, const float* __restrict__ p3,
    float* __restrict__ out, int mode,
    float* __restrict__ out2, float* __restrict__ out3,
    float* __restrict__ out3t, float* __restrict__ out2t)
{
    extern __shared__ __align__(128) char smem[];
    const uint32_t sb = smem_u32(smem);
    const int t = threadIdx.x;
    const int warp = t >> 5, lane = t & 31;
    const int nog = Cout >> 7;
    const int ocg = blockIdx.y % nog;
    const int b   = blockIdx.y / nog;
    const int y0  = blockIdx.x * 2;
    const int ocb = ocg * 128;

    const int q8 = t & 7;
    const int r0 = t >> 3;

    const int T = chunks * ntap;

    auto issue_tile = [&](int i) {
        const int c   = i / ntap;
        const int tap = i - c*ntap;
        const int dy  = (ntap == 1) ? 1 : tap / 3;
        const int dx  = (ntap == 1) ? 1 : tap - (tap/3)*3;
        const int ic0 = c * 64;
        const uint32_t base = sb + (uint32_t)(i % 3) * STAGE_B;
        #pragma unroll
        for (int p = 0; p < 4; p++) {
            const int m = r0 + 32*p;
            const uint32_t so = sw128((uint32_t)(m*128 + q8*16));
            cpa16(base + OFF_A + so,
                  Wh + (size_t)(tap*Cout + ocb + m)*Ctot + ic0 + q8*8);
            const int yl = m >> 6, x = m & 63;
            cpa16(base + OFF_B + so,
                  Xh + ((size_t)(b*66 + y0 + yl + dy)*66 + (x + dx))*pitch + ic0 + q8*8);
        }
        cpa_commit();
    };

    const int m0 = (warp >> 2) * 64;
    const int n0 = (warp & 3) * 32;
    float acc[4][4][4];
    #pragma unroll
    for (int mi = 0; mi < 4; mi++)
        #pragma unroll
        for (int nj = 0; nj < 4; nj++)
            #pragma unroll
            for (int u = 0; u < 4; u++) acc[mi][nj][u] = 0.f;

    const int arow  = lane & 15;
    const int acolb = ((lane >> 4) << 3) * 2;
    const int brow  = (lane & 7) + ((lane >> 4) << 3);
    const int bcolb = (((lane >> 3) & 1) << 3) * 2;

    issue_tile(0);
    if (T > 1) issue_tile(1);

    for (int i = 0; i < T; i++) {
        if (i + 1 < T) cpa_wait1();
        else           cpa_wait0();
        __syncthreads();
        if (i + 2 < T) issue_tile(i + 2);

        const uint32_t base = sb + (uint32_t)(i % 3) * STAGE_B;
        const uint32_t sA = base + OFF_A;
        const uint32_t sB = base + OFF_B;

        #pragma unroll
        for (int kk = 0; kk < 4; kk++) {
            const int k0b = kk * 32;
            uint32_t a[4][4], bh[2][4];
            #pragma unroll
            for (int mi = 0; mi < 4; mi++) {
                const uint32_t ro = sw128((uint32_t)((m0 + mi*16 + arow) * 128 + k0b + acolb));
                ldsm4(a[mi], sA + ro);
            }
            #pragma unroll
            for (int ni = 0; ni < 2; ni++) {
                const uint32_t ro = sw128((uint32_t)((n0 + ni*16 + brow) * 128 + k0b + bcolb));
                ldsm4(bh[ni], sB + ro);
            }
            #pragma unroll
            for (int mi = 0; mi < 4; mi++)
                #pragma unroll
                for (int nj = 0; nj < 4; nj++)
                    mma16816(acc[mi][nj], a[mi], &bh[nj >> 1][(nj & 1) * 2]);
        }
    }

    // ---- epilogue ----
    const int g  = lane >> 2;
    const int t2 = (lane & 3) * 2;
    #pragma unroll
    for (int mi = 0; mi < 4; mi++) {
        const int ocA = ocb + m0 + mi*16 + g;
        const int ocB = ocA + 8;
        float scA = 1.f, biA = 0.f, scB = 1.f, biB = 0.f;
        if (mode == 0) {
            scA = p0[ocA] * rsqrtf(p3[ocA] + 1e-5f);
            biA = p1[ocA] - p2[ocA] * scA;
            scB = p0[ocB] * rsqrtf(p3[ocB] + 1e-5f);
            biB = p1[ocB] - p2[ocB] * scB;
        }
        #pragma unroll
        for (int nj = 0; nj < 4; nj++) {
            const int n  = n0 + nj*8 + t2;
            const int yl = n >> 6, x = n & 63;
            const int py = y0 + yl;
            float v0 = acc[mi][nj][0], v1 = acc[mi][nj][1];
            float v2 = acc[mi][nj][2], v3 = acc[mi][nj][3];
            if (mode == 3) {
                #pragma unroll
                for (int h = 0; h < 2; h++) {
                    const int oc = h ? ocB : ocA;
                    float u0 = h ? v2 : v0;
                    float u1 = h ? v3 : v1;
                    if (oc < 16) {
                        float bi = p0[oc];
                        *(float2*)&out[((size_t)(b*CQ + oc)*64 + py)*64 + x] =
                            make_float2(u0 + bi, u1 + bi);
                    } else if (oc < 32) {
                        const int c = oc - 16;
                        float bi = p1[c];
                        u0 += bi; u1 += bi;
                        *(float2*)&out2[((size_t)(b*CQ + c)*64 + py)*64 + x] =
                            make_float2(u0, u1);
                        out2t[((size_t)(b*CQ + c)*64 + x    )*64 + py] = u0;
                        out2t[((size_t)(b*CQ + c)*64 + x + 1)*64 + py] = u1;
                    } else if (oc < 160) {
                        const int c = oc - 32;
                        float bi = p2[c];
                        u0 += bi; u1 += bi;
                        *(float2*)&out3[((size_t)(b*CI + c)*64 + py)*64 + x] =
                            make_float2(u0, u1);
                        out3t[((size_t)(b*CI + c)*64 + x    )*64 + py] = u0;
                        out3t[((size_t)(b*CI + c)*64 + x + 1)*64 + py] = u1;
                    }
                }
                continue;
            }
            if (mode == 0) {
                v0 = v0*scA + biA; v1 = v1*scA + biA;
                v2 = v2*scB + biB; v3 = v3*scB + biB;
            } else {
                if (v0 <= 0.f) v0 = 512.0f * expm1f(v0);
                if (v1 <= 0.f) v1 = 512.0f * expm1f(v1);
                if (v2 <= 0.f) v2 = 512.0f * expm1f(v2);
                if (v3 <= 0.f) v3 = 512.0f * expm1f(v3);
            }
            *(float2*)&out[((size_t)(b*Cout + ocA)*64 + py)*64 + x] = make_float2(v0, v1);
            *(float2*)&out[((size_t)(b*Cout + ocB)*64 + py)*64 + x] = make_float2(v2, v3);
        }
    }
}

// =====================================================================
// att_k: logits + softmax -> fp16 att [b,h,w][128]
// =====================================================================
__global__ void __launch_bounds__(256) att_k(
    const float* __restrict__ q, const float* __restrict__ k,
    const float* __restrict__ kt, __half* __restrict__ att)
{
    __shared__ float qs[16*64];
    __shared__ float ks[16*64];
    __shared__ float E[64*128];

    const int t = threadIdx.x;
    const int h = blockIdx.x, b = blockIdx.y;

    for (int idx = t; idx < 1024; idx += 256) {
        int c = idx >> 6, w = idx & 63;
        qs[idx] = q[((b*CQ + c)*HH + h)*WW + w];
        ks[idx] = k[((b*CQ + c)*HH + h)*WW + w];
    }
    __syncthreads();

    for (int idx = t; idx < 2048; idx += 256) {
        const int w  = idx >> 5;
        const int j4 = idx & 31;
        float4 e = make_float4(0.f, 0.f, 0.f, 0.f);
        if (j4 < 16) {
            for (int c = 0; c < 16; c++) {
                float qq = qs[c*64 + w];
                float4 kv = ((const float4*)kt)[((b*CQ + c)*WW + w)*16 + j4];
                e.x += qq * kv.x; e.y += qq * kv.y; e.z += qq * kv.z; e.w += qq * kv.w;
            }
            if ((h >> 2) == j4) ((float*)&e)[h & 3] = -INFINITY;
        } else {
            for (int c = 0; c < 16; c++) {
                float qq = qs[c*64 + w];
                float4 kv = ((const float4*)ks)[c*16 + (j4 - 16)];
                e.x += qq * kv.x; e.y += qq * kv.y; e.z += qq * kv.z; e.w += qq * kv.w;
            }
        }
        ((float4*)E)[w*32 + j4] = e;
    }
    __syncthreads();

    const int lane = t & 31, wid = t >> 5;
    for (int r = 0; r < 8; r++) {
        const int w = wid*8 + r;
        float v0 = E[w*128 + lane],      v1 = E[w*128 + lane + 32];
        float v2 = E[w*128 + lane + 64], v3 = E[w*128 + lane + 96];
        float m = fmaxf(fmaxf(v0, v1), fmaxf(v2, v3));
        #pragma unroll
        for (int s = 16; s; s >>= 1) m = fmaxf(m, __shfl_xor_sync(0xffffffffu, m, s));
        float e0 = expf(v0 - m), e1 = expf(v1 - m), e2 = expf(v2 - m), e3 = expf(v3 - m);
        float sum = e0 + e1 + e2 + e3;
        #pragma unroll
        for (int s = 16; s; s >>= 1) sum += __shfl_xor_sync(0xffffffffu, sum, s);
        float inv = 1.f / sum;
        __half* dst = att + (size_t)((b*HH + h)*WW + w)*128;
        dst[lane]      = __float2half_rn(e0*inv);
        dst[lane + 32] = __float2half_rn(e1*inv);
        dst[lane + 64] = __float2half_rn(e2*inv);
        dst[lane + 96] = __float2half_rn(e3*inv);
    }
}

// =====================================================================
// oHmma_k (store-only): per (b,w): C[c][h] = sum_g vt[c,g]*aH[h,g] via
// HMMA; stores RAW oH into G (same scattered store-only pattern as the
// old FFMA oH_k — no RMW).
// oWmma_k: per (b,h): C[c][w] = sum_wp v[c,wp]*aW[w,wp] via HMMA;
//          G = feat + gamma*(G_prev(oH) + C)  (coalesced float2 RMW).
// =====================================================================
#define AGG_VA   0
#define AGG_AW   16384
#define AGG_SMEM (16384 + 8192)

__global__ void __launch_bounds__(256) oHmma_k(
    const __half* __restrict__ att, const float* __restrict__ vt,
    float* __restrict__ G)
{
    extern __shared__ __align__(128) char smem[];
    const uint32_t sb = smem_u32(smem);
    const int t = threadIdx.x;
    const int warp = t >> 5, lane = t & 31;
    const int w = blockIdx.x, b = blockIdx.y;

    // Va[c][g] <- fp16(vt[b,c,w,g])
    for (int idx = t; idx < 1024; idx += 256) {
        const int c = idx >> 3, qq = idx & 7;
        float f[8];
        *(float4*)&f[0] = *(const float4*)(vt + ((size_t)(b*CI + c)*64 + w)*64 + qq*8);
        *(float4*)&f[4] = *(const float4*)(vt + ((size_t)(b*CI + c)*64 + w)*64 + qq*8 + 4);
        *(uint4*)(smem + AGG_VA + sw128((uint32_t)(c*128 + qq*16))) = pack8h(f);
    }
    // Ah[hh][g] <- att[b,hh,w][g]
    for (int idx = t; idx < 512; idx += 256) {
        const int hh = idx >> 3, qq = idx & 7;
        uint4 u = *(const uint4*)(att + (size_t)((b*HH + hh)*WW + w)*128 + qq*8);
        *(uint4*)(smem + AGG_AW + sw128((uint32_t)(hh*128 + qq*16))) = u;
    }
    __syncthreads();

    const int m0 = (warp >> 2) * 64;
    const int n0 = (warp & 3) * 16;
    float acc[4][2][4];
    #pragma unroll
    for (int mi = 0; mi < 4; mi++)
        #pragma unroll
        for (int nj = 0; nj < 2; nj++)
            #pragma unroll
            for (int u = 0; u < 4; u++) acc[mi][nj][u] = 0.f;

    const int arow  = lane & 15;
    const int acolb = ((lane >> 4) << 3) * 2;
    const int brow  = (lane & 7) + ((lane >> 4) << 3);
    const int bcolb = (((lane >> 3) & 1) << 3) * 2;

    #pragma unroll
    for (int kk = 0; kk < 4; kk++) {
        const int k0b = kk * 32;
        uint32_t a[4][4], bh[4];
        #pragma unroll
        for (int mi = 0; mi < 4; mi++)
            ldsm4(a[mi], sb + AGG_VA + sw128((uint32_t)((m0 + mi*16 + arow)*128 + k0b + acolb)));
        ldsm4(bh, sb + AGG_AW + sw128((uint32_t)((n0 + brow)*128 + k0b + bcolb)));
        #pragma unroll
        for (int mi = 0; mi < 4; mi++)
            #pragma unroll
            for (int nj = 0; nj < 2; nj++)
                mma16816(acc[mi][nj], a[mi], &bh[nj*2]);
    }

    const int g  = lane >> 2;
    const int t2 = (lane & 3) * 2;
    #pragma unroll
    for (int mi = 0; mi < 4; mi++) {
        const int cA = m0 + mi*16 + g;
        const int cB = cA + 8;
        #pragma unroll
        for (int nj = 0; nj < 2; nj++) {
            const int n = n0 + nj*8 + t2;   // h index
            const size_t iA0 = ((size_t)(b*CI + cA)*64 + n)*64 + w;
            const size_t iB0 = ((size_t)(b*CI + cB)*64 + n)*64 + w;
            G[iA0]      = acc[mi][nj][0];
            G[iA0 + 64] = acc[mi][nj][1];
            G[iB0]      = acc[mi][nj][2];
            G[iB0 + 64] = acc[mi][nj][3];
        }
    }
}

__global__ void __launch_bounds__(256) oWmma_k(
    const __half* __restrict__ att, const float* __restrict__ v,
    const float* __restrict__ feat, const float* __restrict__ gamma,
    float* __restrict__ G)
{
    extern __shared__ __align__(128) char smem[];
    const uint32_t sb = smem_u32(smem);
    const int t = threadIdx.x;
    const int warp = t >> 5, lane = t & 31;
    const int h = blockIdx.x, b = blockIdx.y;

    // Va[c][wp] <- fp16(v[b,c,h,wp])
    for (int idx = t; idx < 1024; idx += 256) {
        const int c = idx >> 3, qq = idx & 7;
        float f[8];
        *(float4*)&f[0] = *(const float4*)(v + ((size_t)(b*CI + c)*64 + h)*64 + qq*8);
        *(float4*)&f[4] = *(const float4*)(v + ((size_t)(b*CI + c)*64 + h)*64 + qq*8 + 4);
        *(uint4*)(smem + AGG_VA + sw128((uint32_t)(c*128 + qq*16))) = pack8h(f);
    }
    // Aw[w][wp] <- att[b,h,w][64+wp]
    for (int idx = t; idx < 512; idx += 256) {
        const int w = idx >> 3, qq = idx & 7;
        uint4 u = *(const uint4*)(att + (size_t)((b*HH + h)*WW + w)*128 + 64 + qq*8);
        *(uint4*)(smem + AGG_AW + sw128((uint32_t)(w*128 + qq*16))) = u;
    }
    __syncthreads();

    const int m0 = (warp >> 2) * 64;
    const int n0 = (warp & 3) * 16;
    float acc[4][2][4];
    #pragma unroll
    for (int mi = 0; mi < 4; mi++)
        #pragma unroll
        for (int nj = 0; nj < 2; nj++)
            #pragma unroll
            for (int u = 0; u < 4; u++) acc[mi][nj][u] = 0.f;

    const int arow  = lane & 15;
    const int acolb = ((lane >> 4) << 3) * 2;
    const int brow  = (lane & 7) + ((lane >> 4) << 3);
    const int bcolb = (((lane >> 3) & 1) << 3) * 2;

    #pragma unroll
    for (int kk = 0; kk < 4; kk++) {
        const int k0b = kk * 32;
        uint32_t a[4][4], bh[4];
        #pragma unroll
        for (int mi = 0; mi < 4; mi++)
            ldsm4(a[mi], sb + AGG_VA + sw128((uint32_t)((m0 + mi*16 + arow)*128 + k0b + acolb)));
        ldsm4(bh, sb + AGG_AW + sw128((uint32_t)((n0 + brow)*128 + k0b + bcolb)));
        #pragma unroll
        for (int mi = 0; mi < 4; mi++)
            #pragma unroll
            for (int nj = 0; nj < 2; nj++)
                mma16816(acc[mi][nj], a[mi], &bh[nj*2]);
    }

    const float gm = gamma[0];
    const int g  = lane >> 2;
    const int t2 = (lane & 3) * 2;
    #pragma unroll
    for (int mi = 0; mi < 4; mi++) {
        const int cA = m0 + mi*16 + g;
        const int cB = cA + 8;
        #pragma unroll
        for (int nj = 0; nj < 2; nj++) {
            const int n = n0 + nj*8 + t2;
            const size_t iA = ((size_t)(b*CI + cA)*64 + h)*64 + n;
            const size_t iB = ((size_t)(b*CI + cB)*64 + h)*64 + n;
            float2 fA = *(const float2*)(feat + iA);
            float2 fB = *(const float2*)(feat + iB);
            float2 gA = *(const float2*)(G + iA);     // raw oH
            float2 gB = *(const float2*)(G + iB);
            *(float2*)(G + iA) = make_float2(fA.x + gm*(gA.x + acc[mi][nj][0]),
                                             fA.y + gm*(gA.y + acc[mi][nj][1]));
            *(float2*)(G + iB) = make_float2(fB.x + gm*(gB.x + acc[mi][nj][2]),
                                             fB.y + gm*(gB.y + acc[mi][nj][3]));
        }
    }
}

// =====================================================================
extern "C" void kernel_launch(void* const* d_in, const int* in_sizes, int n_in,
                              void* d_out, int out_size)
{
    (void)in_sizes; (void)n_in; (void)out_size;
    const float* x       = (const float*)d_in[0];
    const float* conva_w = (const float*)d_in[1];
    const float* bn1_g   = (const float*)d_in[2];
    const float* bn1_b   = (const float*)d_in[3];
    const float* bn1_m   = (const float*)d_in[4];
    const float* bn1_v   = (const float*)d_in[5];
    const float* wq      = (const float*)d_in[6];
    const float* bq      = (const float*)d_in[7];
    const float* wk      = (const float*)d_in[8];
    const float* bk      = (const float*)d_in[9];
    const float* wv      = (const float*)d_in[10];
    const float* bv      = (const float*)d_in[11];
    const float* gamma   = (const float*)d_in[12];
    const float* convb_w = (const float*)d_in[13];
    const float* bn2_g   = (const float*)d_in[14];
    const float* bn2_b   = (const float*)d_in[15];
    const float* bn2_m   = (const float*)d_in[16];
    const float* bn2_v   = (const float*)d_in[17];
    const float* bott_w  = (const float*)d_in[18];
    float* out = (float*)d_out;

    float *featA, *featB, *qb, *kb, *ktb, *vb, *vtb;
    __half* attb;
    cudaGetSymbolAddress((void**)&featA, g_featA);
    cudaGetSymbolAddress((void**)&featB, g_featB);
    cudaGetSymbolAddress((void**)&qb,    g_q);
    cudaGetSymbolAddress((void**)&kb,    g_k);
    cudaGetSymbolAddress((void**)&ktb,   g_kt);
    cudaGetSymbolAddress((void**)&vb,    g_v);
    cudaGetSymbolAddress((void**)&vtb,   g_vt);
    cudaGetSymbolAddress((void**)&attb,  g_att4);

    __half *xph, *x2h, *whi, *wqkv;
    cudaGetSymbolAddress((void**)&xph,  g_xph4);
    cudaGetSymbolAddress((void**)&x2h,  g_x2h4);
    cudaGetSymbolAddress((void**)&whi,  g_whi4);
    cudaGetSymbolAddress((void**)&wqkv, g_wqkv4);

    cudaFuncSetAttribute(oHmma_k,   cudaFuncAttributeMaxDynamicSharedMemorySize, AGG_SMEM);
    cudaFuncSetAttribute(oWmma_k,   cudaFuncAttributeMaxDynamicSharedMemorySize, AGG_SMEM);
    cudaFuncSetAttribute(convmma_k, cudaFuncAttributeMaxDynamicSharedMemorySize, SM_TOTAL);

    // ---- conv1 (512 -> 128) + BN1 ----
    wprep_k<<<512, 256>>>(conva_w, CI, CIN, whi);
    pad_k<<<dim3(64, CIN/64, BB), 256>>>(x, CIN, xph, 640, 0);
    zero_border_k<<<1024, 256>>>(xph, 640);
    convmma_k<<<dim3(32, BB), 256, SM_TOTAL>>>(xph, 640, CIN/64, 9,
                                               whi, CIN, CI,
                                               bn1_g, bn1_b, bn1_m, bn1_v,
                                               featA, 0, nullptr, nullptr, nullptr, nullptr);

    // ---- criss-cross attention x2 (qkv via HMMA 1x1 conv; k->kt, v->vt fused) ----
    wprep_qkv_k<<<128, 256>>>(wq, wk, wv, wqkv);
    zero_border_k<<<1024, 256>>>(x2h, 128);
    float* F = featA;
    float* G = featB;
    for (int it = 0; it < 2; it++) {
        pad_k<<<dim3(64, CI/64, BB), 256>>>(F, CI, x2h, 128, 0);
        convmma_k<<<dim3(32, BB*2), 256, SM_TOTAL>>>(x2h, 128, CI/64, 1,
                                                     wqkv, CI, 256,
                                                     bq, bk, bv, nullptr,
                                                     qb, 3, kb, vb, vtb, ktb);
        att_k<<<dim3(HH, BB), 256>>>(qb, kb, ktb, attb);
        oHmma_k<<<dim3(WW, BB), 256, AGG_SMEM>>>(attb, vtb, G);
        oWmma_k<<<dim3(HH, BB), 256, AGG_SMEM>>>(attb, vb, F, gamma, G);
        float* tmp = F; F = G; G = tmp;
    }
    // after 2 iters: F = featA, G = featB

    // ---- convb (128 -> 128) + BN2 ----
    wprep_k<<<576, 256>>>(convb_w, CI, CI, whi);
    pad_k<<<dim3(64, CI/64, BB), 256>>>(F, CI, x2h, 128, 0);
    convmma_k<<<dim3(32, BB), 256, SM_TOTAL>>>(x2h, 128, CI/64, 9,
                                               whi, CI, CI,
                                               bn2_g, bn2_b, bn2_m, bn2_v,
                                               G, 0, nullptr, nullptr, nullptr, nullptr);

    // ---- bottleneck conv (concat 512+128 -> 512) + ELU ----
    pad_k<<<dim3(64, CI/64, BB), 256>>>(G, CI, xph, 640, CIN);
    wprep_k<<<4096, 256>>>(bott_w, CIN, CIN + CI, whi);
    convmma_k<<<dim3(32, BB*(CIN/128)), 256, SM_TOTAL>>>(xph, 640, (CIN + CI)/64, 9,
                                                         whi, CIN + CI, CIN,
                                                         nullptr, nullptr, nullptr, nullptr,
                                                         out, 1, nullptr, nullptr, nullptr, nullptr);
}

// round 15
// speedup vs baseline: 1.1926x; 1.0283x over previous
#include <cuda_runtime.h>
#include <cuda_fp16.h>
#include <math.h>
#include <stdint.h>

#define BB 8
#define HH 64
#define WW 64
#define HWSZ 4096
#define CI 128
#define CQ 16
#define CIN 512

// ---------------- scratch buffers (static device allocations) ----------------
__device__ float g_featA[BB*CI*HWSZ];
__device__ float g_featB[BB*CI*HWSZ];
__device__ float g_q [BB*CQ*HWSZ];
__device__ float g_k [BB*CQ*HWSZ];
__device__ float g_kt[BB*CQ*HWSZ];
__device__ float g_v [BB*CI*HWSZ];
__device__ float g_vt[BB*CI*HWSZ];
__device__ uint4 g_att4[(8ULL*HH*WW*128*2)/16];   // fp16 att [b,h,w][128]

// padded NHWC fp16 feature maps (16B aligned via uint4)
#define XP640_ELEMS (8ULL*66*66*640)
#define XP128_ELEMS (8ULL*66*66*128)
#define WSP_ELEMS   (9ULL*512*640)
__device__ uint4 g_xph4[XP640_ELEMS/8];
__device__ uint4 g_x2h4[XP128_ELEMS/8];
__device__ uint4 g_whi4[WSP_ELEMS/8];
__device__ uint4 g_wqkv4[(256*128)/8];   // packed q|k|v|pad weights, fp16

// =====================================================================
// PTX helpers (compute_103-safe: mma.sync / ldmatrix / cp.async only)
// =====================================================================
__device__ __forceinline__ uint32_t smem_u32(const void* p) {
    uint32_t a;
    asm("{ .reg .u64 t; cvta.to.shared.u64 t, %1; cvt.u32.u64 %0, t; }" : "=r"(a) : "l"(p));
    return a;
}
__device__ __forceinline__ void cpa16(uint32_t dst, const void* src) {
    asm volatile("cp.async.cg.shared.global [%0], [%1], 16;" :: "r"(dst), "l"(src) : "memory");
}
__device__ __forceinline__ void cpa_commit() {
    asm volatile("cp.async.commit_group;" ::: "memory");
}
__device__ __forceinline__ void cpa_wait1() {
    asm volatile("cp.async.wait_group 1;" ::: "memory");
}
__device__ __forceinline__ void cpa_wait0() {
    asm volatile("cp.async.wait_group 0;" ::: "memory");
}
__device__ __forceinline__ void ldsm4(uint32_t* r, uint32_t addr) {
    asm volatile("ldmatrix.sync.aligned.m8n8.x4.shared.b16 {%0,%1,%2,%3}, [%4];"
                 : "=r"(r[0]), "=r"(r[1]), "=r"(r[2]), "=r"(r[3]) : "r"(addr));
}
__device__ __forceinline__ void mma16816(float* c, const uint32_t* a, const uint32_t* b) {
    asm volatile(
        "mma.sync.aligned.m16n8k16.row.col.f32.f16.f16.f32 "
        "{%0,%1,%2,%3}, {%4,%5,%6,%7}, {%8,%9}, {%0,%1,%2,%3};"
        : "+f"(c[0]), "+f"(c[1]), "+f"(c[2]), "+f"(c[3])
        : "r"(a[0]), "r"(a[1]), "r"(a[2]), "r"(a[3]), "r"(b[0]), "r"(b[1]));
}
__device__ __forceinline__ uint32_t sw128(uint32_t off) {
    return off ^ ((off >> 3) & 0x70);
}
__device__ __forceinline__ uint4 pack8h(const float* f) {
    __half2 h0 = __floats2half2_rn(f[0], f[1]);
    __half2 h1 = __floats2half2_rn(f[2], f[3]);
    __half2 h2 = __floats2half2_rn(f[4], f[5]);
    __half2 h3 = __floats2half2_rn(f[6], f[7]);
    uint4 u;
    u.x = *(uint32_t*)&h0; u.y = *(uint32_t*)&h1;
    u.z = *(uint32_t*)&h2; u.w = *(uint32_t*)&h3;
    return u;
}

// =====================================================================
// prep: NCHW fp32 -> padded NHWC fp16 (interior only)
// =====================================================================
__global__ void __launch_bounds__(256) pad_k(
    const float* __restrict__ src, int C,
    __half* __restrict__ dh, int pitch, int colofs)
{
    __shared__ float s[64][65];
    const int y = blockIdx.x, cbase = blockIdx.y * 64, b = blockIdx.z;
    const int t = threadIdx.x;
    for (int idx = t; idx < 4096; idx += 256) {
        int icl = idx >> 6, x = idx & 63;
        s[icl][x] = src[((size_t)(b*C + cbase + icl)*64 + y)*64 + x];
    }
    __syncthreads();
    for (int idx = t; idx < 4096; idx += 256) {
        int x = idx >> 6, icl = idx & 63;
        size_t o = ((size_t)(b*66 + y + 1)*66 + (x + 1))*pitch + colofs + cbase + icl;
        dh[o] = __float2half_rn(s[icl][x]);
    }
}

__global__ void __launch_bounds__(256) zero_border_k(
    __half* __restrict__ dh, int pitch)
{
    const int total = 8 * 260 * pitch;
    for (int idx = blockIdx.x*256 + threadIdx.x; idx < total; idx += gridDim.x*256) {
        int ic = idx % pitch;
        int r  = idx / pitch;
        int b  = r / 260;
        int pos = r % 260;
        int yy, xx;
        if      (pos < 66)  { yy = 0;  xx = pos; }
        else if (pos < 132) { yy = 65; xx = pos - 66; }
        else if (pos < 196) { yy = pos - 132 + 1; xx = 0; }
        else                { yy = pos - 196 + 1; xx = 65; }
        dh[((size_t)(b*66 + yy)*66 + xx)*pitch + ic] = __float2half_rn(0.f);
    }
}

// weights: w[oc][ic][3][3] fp32 -> Wh [tap][oc][ic] fp16
__global__ void __launch_bounds__(256) wprep_k(
    const float* __restrict__ w, int Cout, int Ctot,
    __half* __restrict__ wh)
{
    const int total = Cout * Ctot * 9;
    for (int idx = blockIdx.x*256 + threadIdx.x; idx < total; idx += gridDim.x*256) {
        int ic  = idx % Ctot;
        int r   = idx / Ctot;
        int oc  = r % Cout;
        int tap = r / Cout;
        wh[(size_t)(tap*Cout + oc)*Ctot + ic] =
            __float2half_rn(w[(size_t)(oc*Ctot + ic)*9 + tap]);
    }
}

// packed qkv weights: [256 oc][128 ic] fp16 = q(16) | k(16) | v(128) | zeros(96)
__global__ void __launch_bounds__(256) wprep_qkv_k(
    const float* __restrict__ wq, const float* __restrict__ wk,
    const float* __restrict__ wv, __half* __restrict__ wh)
{
    const int total = 256 * 128;
    for (int idx = blockIdx.x*256 + threadIdx.x; idx < total; idx += gridDim.x*256) {
        int oc = idx >> 7, ic = idx & 127;
        float v = 0.f;
        if      (oc < 16)  v = wq[oc*128 + ic];
        else if (oc < 32)  v = wk[(oc-16)*128 + ic];
        else if (oc < 160) v = wv[(oc-32)*128 + ic];
        wh[idx] = __float2half_rn(v);
    }
}

// =====================================================================
// HMMA implicit-GEMM conv (frozen mainloop).
// modes: 0 = BN (+ optional fp16 xpad write, pitch 128),
//        1 = ELU(512), 3 = qkv scatter (q, k + kt, v + vt)
// =====================================================================
#define TILE_B (128*128)
#define OFF_A  0
#define OFF_B  TILE_B
#define STAGE_B (2*TILE_B)
#define SM_TOTAL (3*STAGE_B)

__global__ void __launch_bounds__(256, 2) convmma_k(
    const __half* __restrict__ Xh,
    int pitch, int chunks, int ntap,
    const __half* __restrict__ Wh,
    int Ctot, int Cout,
    const float* __restrict__ p0, const float* __restrict__ p1,
    const float* __restrict__ p2, const float* __restrict__ p3,
    float* __restrict__ out, int mode,
    float* __restrict__ out2, float* __restrict__ out3,
    float* __restrict__ out3t, float* __restrict__ out2t,
    __half* __restrict__ xpad)
{
    extern __shared__ __align__(128) char smem[];
    const uint32_t sb = smem_u32(smem);
    const int t = threadIdx.x;
    const int warp = t >> 5, lane = t & 31;
    const int nog = Cout >> 7;
    const int ocg = blockIdx.y % nog;
    const int b   = blockIdx.y / nog;
    const int y0  = blockIdx.x * 2;
    const int ocb = ocg * 128;

    const int q8 = t & 7;
    const int r0 = t >> 3;

    const int T = chunks * ntap;

    auto issue_tile = [&](int i) {
        const int c   = i / ntap;
        const int tap = i - c*ntap;
        const int dy  = (ntap == 1) ? 1 : tap / 3;
        const int dx  = (ntap == 1) ? 1 : tap - (tap/3)*3;
        const int ic0 = c * 64;
        const uint32_t base = sb + (uint32_t)(i % 3) * STAGE_B;
        #pragma unroll
        for (int p = 0; p < 4; p++) {
            const int m = r0 + 32*p;
            const uint32_t so = sw128((uint32_t)(m*128 + q8*16));
            cpa16(base + OFF_A + so,
                  Wh + (size_t)(tap*Cout + ocb + m)*Ctot + ic0 + q8*8);
            const int yl = m >> 6, x = m & 63;
            cpa16(base + OFF_B + so,
                  Xh + ((size_t)(b*66 + y0 + yl + dy)*66 + (x + dx))*pitch + ic0 + q8*8);
        }
        cpa_commit();
    };

    const int m0 = (warp >> 2) * 64;
    const int n0 = (warp & 3) * 32;
    float acc[4][4][4];
    #pragma unroll
    for (int mi = 0; mi < 4; mi++)
        #pragma unroll
        for (int nj = 0; nj < 4; nj++)
            #pragma unroll
            for (int u = 0; u < 4; u++) acc[mi][nj][u] = 0.f;

    const int arow  = lane & 15;
    const int acolb = ((lane >> 4) << 3) * 2;
    const int brow  = (lane & 7) + ((lane >> 4) << 3);
    const int bcolb = (((lane >> 3) & 1) << 3) * 2;

    issue_tile(0);
    if (T > 1) issue_tile(1);

    for (int i = 0; i < T; i++) {
        if (i + 1 < T) cpa_wait1();
        else           cpa_wait0();
        __syncthreads();
        if (i + 2 < T) issue_tile(i + 2);

        const uint32_t base = sb + (uint32_t)(i % 3) * STAGE_B;
        const uint32_t sA = base + OFF_A;
        const uint32_t sB = base + OFF_B;

        #pragma unroll
        for (int kk = 0; kk < 4; kk++) {
            const int k0b = kk * 32;
            uint32_t a[4][4], bh[2][4];
            #pragma unroll
            for (int mi = 0; mi < 4; mi++) {
                const uint32_t ro = sw128((uint32_t)((m0 + mi*16 + arow) * 128 + k0b + acolb));
                ldsm4(a[mi], sA + ro);
            }
            #pragma unroll
            for (int ni = 0; ni < 2; ni++) {
                const uint32_t ro = sw128((uint32_t)((n0 + ni*16 + brow) * 128 + k0b + bcolb));
                ldsm4(bh[ni], sB + ro);
            }
            #pragma unroll
            for (int mi = 0; mi < 4; mi++)
                #pragma unroll
                for (int nj = 0; nj < 4; nj++)
                    mma16816(acc[mi][nj], a[mi], &bh[nj >> 1][(nj & 1) * 2]);
        }
    }

    // ---- epilogue ----
    const int g  = lane >> 2;
    const int t2 = (lane & 3) * 2;
    #pragma unroll
    for (int mi = 0; mi < 4; mi++) {
        const int ocA = ocb + m0 + mi*16 + g;
        const int ocB = ocA + 8;
        float scA = 1.f, biA = 0.f, scB = 1.f, biB = 0.f;
        if (mode == 0) {
            scA = p0[ocA] * rsqrtf(p3[ocA] + 1e-5f);
            biA = p1[ocA] - p2[ocA] * scA;
            scB = p0[ocB] * rsqrtf(p3[ocB] + 1e-5f);
            biB = p1[ocB] - p2[ocB] * scB;
        }
        #pragma unroll
        for (int nj = 0; nj < 4; nj++) {
            const int n  = n0 + nj*8 + t2;
            const int yl = n >> 6, x = n & 63;
            const int py = y0 + yl;
            float v0 = acc[mi][nj][0], v1 = acc[mi][nj][1];
            float v2 = acc[mi][nj][2], v3 = acc[mi][nj][3];
            if (mode == 3) {
                #pragma unroll
                for (int h = 0; h < 2; h++) {
                    const int oc = h ? ocB : ocA;
                    float u0 = h ? v2 : v0;
                    float u1 = h ? v3 : v1;
                    if (oc < 16) {
                        float bi = p0[oc];
                        *(float2*)&out[((size_t)(b*CQ + oc)*64 + py)*64 + x] =
                            make_float2(u0 + bi, u1 + bi);
                    } else if (oc < 32) {
                        const int c = oc - 16;
                        float bi = p1[c];
                        u0 += bi; u1 += bi;
                        *(float2*)&out2[((size_t)(b*CQ + c)*64 + py)*64 + x] =
                            make_float2(u0, u1);
                        out2t[((size_t)(b*CQ + c)*64 + x    )*64 + py] = u0;
                        out2t[((size_t)(b*CQ + c)*64 + x + 1)*64 + py] = u1;
                    } else if (oc < 160) {
                        const int c = oc - 32;
                        float bi = p2[c];
                        u0 += bi; u1 += bi;
                        *(float2*)&out3[((size_t)(b*CI + c)*64 + py)*64 + x] =
                            make_float2(u0, u1);
                        out3t[((size_t)(b*CI + c)*64 + x    )*64 + py] = u0;
                        out3t[((size_t)(b*CI + c)*64 + x + 1)*64 + py] = u1;
                    }
                }
                continue;
            }
            if (mode == 0) {
                v0 = v0*scA + biA; v1 = v1*scA + biA;
                v2 = v2*scB + biB; v3 = v3*scB + biB;
            } else {
                if (v0 <= 0.f) v0 = 512.0f * expm1f(v0);
                if (v1 <= 0.f) v1 = 512.0f * expm1f(v1);
                if (v2 <= 0.f) v2 = 512.0f * expm1f(v2);
                if (v3 <= 0.f) v3 = 512.0f * expm1f(v3);
            }
            *(float2*)&out[((size_t)(b*Cout + ocA)*64 + py)*64 + x] = make_float2(v0, v1);
            *(float2*)&out[((size_t)(b*Cout + ocB)*64 + py)*64 + x] = make_float2(v2, v3);
            if (mode == 0 && xpad) {
                __half* xp = xpad + ((size_t)(b*66 + py + 1)*66 + (x + 1))*128;
                xp[ocA]       = __float2half_rn(v0);
                xp[128 + ocA] = __float2half_rn(v1);
                xp[ocB]       = __float2half_rn(v2);
                xp[128 + ocB] = __float2half_rn(v3);
            }
        }
    }
}

// =====================================================================
// att_k: logits + softmax -> fp16 att [b,h,w][128]
// =====================================================================
__global__ void __launch_bounds__(256) att_k(
    const float* __restrict__ q, const float* __restrict__ k,
    const float* __restrict__ kt, __half* __restrict__ att)
{
    __shared__ float qs[16*64];
    __shared__ float ks[16*64];
    __shared__ float E[64*128];

    const int t = threadIdx.x;
    const int h = blockIdx.x, b = blockIdx.y;

    for (int idx = t; idx < 1024; idx += 256) {
        int c = idx >> 6, w = idx & 63;
        qs[idx] = q[((b*CQ + c)*HH + h)*WW + w];
        ks[idx] = k[((b*CQ + c)*HH + h)*WW + w];
    }
    __syncthreads();

    for (int idx = t; idx < 2048; idx += 256) {
        const int w  = idx >> 5;
        const int j4 = idx & 31;
        float4 e = make_float4(0.f, 0.f, 0.f, 0.f);
        if (j4 < 16) {
            for (int c = 0; c < 16; c++) {
                float qq = qs[c*64 + w];
                float4 kv = ((const float4*)kt)[((b*CQ + c)*WW + w)*16 + j4];
                e.x += qq * kv.x; e.y += qq * kv.y; e.z += qq * kv.z; e.w += qq * kv.w;
            }
            if ((h >> 2) == j4) ((float*)&e)[h & 3] = -INFINITY;
        } else {
            for (int c = 0; c < 16; c++) {
                float qq = qs[c*64 + w];
                float4 kv = ((const float4*)ks)[c*16 + (j4 - 16)];
                e.x += qq * kv.x; e.y += qq * kv.y; e.z += qq * kv.z; e.w += qq * kv.w;
            }
        }
        ((float4*)E)[w*32 + j4] = e;
    }
    __syncthreads();

    const int lane = t & 31, wid = t >> 5;
    for (int r = 0; r < 8; r++) {
        const int w = wid*8 + r;
        float v0 = E[w*128 + lane],      v1 = E[w*128 + lane + 32];
        float v2 = E[w*128 + lane + 64], v3 = E[w*128 + lane + 96];
        float m = fmaxf(fmaxf(v0, v1), fmaxf(v2, v3));
        #pragma unroll
        for (int s = 16; s; s >>= 1) m = fmaxf(m, __shfl_xor_sync(0xffffffffu, m, s));
        float e0 = expf(v0 - m), e1 = expf(v1 - m), e2 = expf(v2 - m), e3 = expf(v3 - m);
        float sum = e0 + e1 + e2 + e3;
        #pragma unroll
        for (int s = 16; s; s >>= 1) sum += __shfl_xor_sync(0xffffffffu, sum, s);
        float inv = 1.f / sum;
        __half* dst = att + (size_t)((b*HH + h)*WW + w)*128;
        dst[lane]      = __float2half_rn(e0*inv);
        dst[lane + 32] = __float2half_rn(e1*inv);
        dst[lane + 64] = __float2half_rn(e2*inv);
        dst[lane + 96] = __float2half_rn(e3*inv);
    }
}

// =====================================================================
// oHmma_k (store-only): raw oH -> G (scattered store-only, no RMW).
// oWmma_k: G = feat + gamma*(G_prev(oH) + oW); optional fp16 xpad write.
// =====================================================================
#define AGG_VA   0
#define AGG_AW   16384
#define AGG_SMEM (16384 + 8192)

__global__ void __launch_bounds__(256) oHmma_k(
    const __half* __restrict__ att, const float* __restrict__ vt,
    float* __restrict__ G)
{
    extern __shared__ __align__(128) char smem[];
    const uint32_t sb = smem_u32(smem);
    const int t = threadIdx.x;
    const int warp = t >> 5, lane = t & 31;
    const int w = blockIdx.x, b = blockIdx.y;

    for (int idx = t; idx < 1024; idx += 256) {
        const int c = idx >> 3, qq = idx & 7;
        float f[8];
        *(float4*)&f[0] = *(const float4*)(vt + ((size_t)(b*CI + c)*64 + w)*64 + qq*8);
        *(float4*)&f[4] = *(const float4*)(vt + ((size_t)(b*CI + c)*64 + w)*64 + qq*8 + 4);
        *(uint4*)(smem + AGG_VA + sw128((uint32_t)(c*128 + qq*16))) = pack8h(f);
    }
    for (int idx = t; idx < 512; idx += 256) {
        const int hh = idx >> 3, qq = idx & 7;
        uint4 u = *(const uint4*)(att + (size_t)((b*HH + hh)*WW + w)*128 + qq*8);
        *(uint4*)(smem + AGG_AW + sw128((uint32_t)(hh*128 + qq*16))) = u;
    }
    __syncthreads();

    const int m0 = (warp >> 2) * 64;
    const int n0 = (warp & 3) * 16;
    float acc[4][2][4];
    #pragma unroll
    for (int mi = 0; mi < 4; mi++)
        #pragma unroll
        for (int nj = 0; nj < 2; nj++)
            #pragma unroll
            for (int u = 0; u < 4; u++) acc[mi][nj][u] = 0.f;

    const int arow  = lane & 15;
    const int acolb = ((lane >> 4) << 3) * 2;
    const int brow  = (lane & 7) + ((lane >> 4) << 3);
    const int bcolb = (((lane >> 3) & 1) << 3) * 2;

    #pragma unroll
    for (int kk = 0; kk < 4; kk++) {
        const int k0b = kk * 32;
        uint32_t a[4][4], bh[4];
        #pragma unroll
        for (int mi = 0; mi < 4; mi++)
            ldsm4(a[mi], sb + AGG_VA + sw128((uint32_t)((m0 + mi*16 + arow)*128 + k0b + acolb)));
        ldsm4(bh, sb + AGG_AW + sw128((uint32_t)((n0 + brow)*128 + k0b + bcolb)));
        #pragma unroll
        for (int mi = 0; mi < 4; mi++)
            #pragma unroll
            for (int nj = 0; nj < 2; nj++)
                mma16816(acc[mi][nj], a[mi], &bh[nj*2]);
    }

    const int g  = lane >> 2;
    const int t2 = (lane & 3) * 2;
    #pragma unroll
    for (int mi = 0; mi < 4; mi++) {
        const int cA = m0 + mi*16 + g;
        const int cB = cA + 8;
        #pragma unroll
        for (int nj = 0; nj < 2; nj++) {
            const int n = n0 + nj*8 + t2;
            const size_t iA0 = ((size_t)(b*CI + cA)*64 + n)*64 + w;
            const size_t iB0 = ((size_t)(b*CI + cB)*64 + n)*64 + w;
            G[iA0]      = acc[mi][nj][0];
            G[iA0 + 64] = acc[mi][nj][1];
            G[iB0]      = acc[mi][nj][2];
            G[iB0 + 64] = acc[mi][nj][3];
        }
    }
}

__global__ void __launch_bounds__(256) oWmma_k(
    const __half* __restrict__ att, const float* __restrict__ v,
    const float* __restrict__ feat, const float* __restrict__ gamma,
    float* __restrict__ G, __half* __restrict__ xpad)
{
    extern __shared__ __align__(128) char smem[];
    const uint32_t sb = smem_u32(smem);
    const int t = threadIdx.x;
    const int warp = t >> 5, lane = t & 31;
    const int h = blockIdx.x, b = blockIdx.y;

    for (int idx = t; idx < 1024; idx += 256) {
        const int c = idx >> 3, qq = idx & 7;
        float f[8];
        *(float4*)&f[0] = *(const float4*)(v + ((size_t)(b*CI + c)*64 + h)*64 + qq*8);
        *(float4*)&f[4] = *(const float4*)(v + ((size_t)(b*CI + c)*64 + h)*64 + qq*8 + 4);
        *(uint4*)(smem + AGG_VA + sw128((uint32_t)(c*128 + qq*16))) = pack8h(f);
    }
    for (int idx = t; idx < 512; idx += 256) {
        const int w = idx >> 3, qq = idx & 7;
        uint4 u = *(const uint4*)(att + (size_t)((b*HH + h)*WW + w)*128 + 64 + qq*8);
        *(uint4*)(smem + AGG_AW + sw128((uint32_t)(w*128 + qq*16))) = u;
    }
    __syncthreads();

    const int m0 = (warp >> 2) * 64;
    const int n0 = (warp & 3) * 16;
    float acc[4][2][4];
    #pragma unroll
    for (int mi = 0; mi < 4; mi++)
        #pragma unroll
        for (int nj = 0; nj < 2; nj++)
            #pragma unroll
            for (int u = 0; u < 4; u++) acc[mi][nj][u] = 0.f;

    const int arow  = lane & 15;
    const int acolb = ((lane >> 4) << 3) * 2;
    const int brow  = (lane & 7) + ((lane >> 4) << 3);
    const int bcolb = (((lane >> 3) & 1) << 3) * 2;

    #pragma unroll
    for (int kk = 0; kk < 4; kk++) {
        const int k0b = kk * 32;
        uint32_t a[4][4], bh[4];
        #pragma unroll
        for (int mi = 0; mi < 4; mi++)
            ldsm4(a[mi], sb + AGG_VA + sw128((uint32_t)((m0 + mi*16 + arow)*128 + k0b + acolb)));
        ldsm4(bh, sb + AGG_AW + sw128((uint32_t)((n0 + brow)*128 + k0b + bcolb)));
        #pragma unroll
        for (int mi = 0; mi < 4; mi++)
            #pragma unroll
            for (int nj = 0; nj < 2; nj++)
                mma16816(acc[mi][nj], a[mi], &bh[nj*2]);
    }

    const float gm = gamma[0];
    const int g  = lane >> 2;
    const int t2 = (lane & 3) * 2;
    #pragma unroll
    for (int mi = 0; mi < 4; mi++) {
        const int cA = m0 + mi*16 + g;
        const int cB = cA + 8;
        #pragma unroll
        for (int nj = 0; nj < 2; nj++) {
            const int n = n0 + nj*8 + t2;
            const size_t iA = ((size_t)(b*CI + cA)*64 + h)*64 + n;
            const size_t iB = ((size_t)(b*CI + cB)*64 + h)*64 + n;
            float2 fA = *(const float2*)(feat + iA);
            float2 fB = *(const float2*)(feat + iB);
            float2 gA = *(const float2*)(G + iA);     // raw oH
            float2 gB = *(const float2*)(G + iB);
            float rA0 = fA.x + gm*(gA.x + acc[mi][nj][0]);
            float rA1 = fA.y + gm*(gA.y + acc[mi][nj][1]);
            float rB0 = fB.x + gm*(gB.x + acc[mi][nj][2]);
            float rB1 = fB.y + gm*(gB.y + acc[mi][nj][3]);
            *(float2*)(G + iA) = make_float2(rA0, rA1);
            *(float2*)(G + iB) = make_float2(rB0, rB1);
            if (xpad) {
                __half* xp = xpad + ((size_t)(b*66 + h + 1)*66 + (n + 1))*128;
                xp[cA]       = __float2half_rn(rA0);
                xp[128 + cA] = __float2half_rn(rA1);
                xp[cB]       = __float2half_rn(rB0);
                xp[128 + cB] = __float2half_rn(rB1);
            }
        }
    }
}

// =====================================================================
extern "C" void kernel_launch(void* const* d_in, const int* in_sizes, int n_in,
                              void* d_out, int out_size)
{
    (void)in_sizes; (void)n_in; (void)out_size;
    const float* x       = (const float*)d_in[0];
    const float* conva_w = (const float*)d_in[1];
    const float* bn1_g   = (const float*)d_in[2];
    const float* bn1_b   = (const float*)d_in[3];
    const float* bn1_m   = (const float*)d_in[4];
    const float* bn1_v   = (const float*)d_in[5];
    const float* wq      = (const float*)d_in[6];
    const float* bq      = (const float*)d_in[7];
    const float* wk      = (const float*)d_in[8];
    const float* bk      = (const float*)d_in[9];
    const float* wv      = (const float*)d_in[10];
    const float* bv      = (const float*)d_in[11];
    const float* gamma   = (const float*)d_in[12];
    const float* convb_w = (const float*)d_in[13];
    const float* bn2_g   = (const float*)d_in[14];
    const float* bn2_b   = (const float*)d_in[15];
    const float* bn2_m   = (const float*)d_in[16];
    const float* bn2_v   = (const float*)d_in[17];
    const float* bott_w  = (const float*)d_in[18];
    float* out = (float*)d_out;

    float *featA, *featB, *qb, *kb, *ktb, *vb, *vtb;
    __half* attb;
    cudaGetSymbolAddress((void**)&featA, g_featA);
    cudaGetSymbolAddress((void**)&featB, g_featB);
    cudaGetSymbolAddress((void**)&qb,    g_q);
    cudaGetSymbolAddress((void**)&kb,    g_k);
    cudaGetSymbolAddress((void**)&ktb,   g_kt);
    cudaGetSymbolAddress((void**)&vb,    g_v);
    cudaGetSymbolAddress((void**)&vtb,   g_vt);
    cudaGetSymbolAddress((void**)&attb,  g_att4);

    __half *xph, *x2h, *whi, *wqkv;
    cudaGetSymbolAddress((void**)&xph,  g_xph4);
    cudaGetSymbolAddress((void**)&x2h,  g_x2h4);
    cudaGetSymbolAddress((void**)&whi,  g_whi4);
    cudaGetSymbolAddress((void**)&wqkv, g_wqkv4);

    cudaFuncSetAttribute(oHmma_k,   cudaFuncAttributeMaxDynamicSharedMemorySize, AGG_SMEM);
    cudaFuncSetAttribute(oWmma_k,   cudaFuncAttributeMaxDynamicSharedMemorySize, AGG_SMEM);
    cudaFuncSetAttribute(convmma_k, cudaFuncAttributeMaxDynamicSharedMemorySize, SM_TOTAL);

    // ---- conv1 (512 -> 128) + BN1 -> featA (fp32) + x2h (fp16 padded) ----
    wprep_k<<<512, 256>>>(conva_w, CI, CIN, whi);
    pad_k<<<dim3(64, CIN/64, BB), 256>>>(x, CIN, xph, 640, 0);
    zero_border_k<<<1024, 256>>>(xph, 640);
    zero_border_k<<<1024, 256>>>(x2h, 128);
    convmma_k<<<dim3(32, BB), 256, SM_TOTAL>>>(xph, 640, CIN/64, 9,
                                               whi, CIN, CI,
                                               bn1_g, bn1_b, bn1_m, bn1_v,
                                               featA, 0, nullptr, nullptr, nullptr, nullptr,
                                               x2h);

    // ---- criss-cross attention x2 (qkv via HMMA 1x1 conv on x2h) ----
    wprep_qkv_k<<<128, 256>>>(wq, wk, wv, wqkv);
    float* F = featA;
    float* G = featB;
    for (int it = 0; it < 2; it++) {
        convmma_k<<<dim3(32, BB*2), 256, SM_TOTAL>>>(x2h, 128, CI/64, 1,
                                                     wqkv, CI, 256,
                                                     bq, bk, bv, nullptr,
                                                     qb, 3, kb, vb, vtb, ktb,
                                                     nullptr);
        att_k<<<dim3(HH, BB), 256>>>(qb, kb, ktb, attb);
        oHmma_k<<<dim3(WW, BB), 256, AGG_SMEM>>>(attb, vtb, G);
        oWmma_k<<<dim3(HH, BB), 256, AGG_SMEM>>>(attb, vb, F, gamma, G, x2h);
        float* tmp = F; F = G; G = tmp;
    }
    // after 2 iters: F = featA, G = featB; x2h holds fp16 of F

    // ---- convb (128 -> 128) + BN2 -> G ----
    wprep_k<<<576, 256>>>(convb_w, CI, CI, whi);
    convmma_k<<<dim3(32, BB), 256, SM_TOTAL>>>(x2h, 128, CI/64, 9,
                                               whi, CI, CI,
                                               bn2_g, bn2_b, bn2_m, bn2_v,
                                               G, 0, nullptr, nullptr, nullptr, nullptr,
                                               nullptr);

    // ---- bottleneck conv (concat 512+128 -> 512) + ELU ----
    pad_k<<<dim3(64, CI/64, BB), 256>>>(G, CI, xph, 640, CIN);
    wprep_k<<<4096, 256>>>(bott_w, CIN, CIN + CI, whi);
    convmma_k<<<dim3(32, BB*(CIN/128)), 256, SM_TOTAL>>>(xph, 640, (CIN + CI)/64, 9,
                                                         whi, CIN + CI, CIN,
                                                         nullptr, nullptr, nullptr, nullptr,
                                                         out, 1, nullptr, nullptr, nullptr, nullptr,
                                                         nullptr);
}

// round 16
// speedup vs baseline: 1.2049x; 1.0103x over previous
#include <cuda_runtime.h>
#include <cuda_fp16.h>
#include <math.h>
#include <stdint.h>

#define BB 8
#define HH 64
#define WW 64
#define HWSZ 4096
#define CI 128
#define CQ 16
#define CIN 512

// ---------------- scratch buffers (static device allocations) ----------------
__device__ float g_featA[BB*CI*HWSZ];
__device__ float g_featB[BB*CI*HWSZ];
__device__ float g_q [BB*CQ*HWSZ];
__device__ float g_k [BB*CQ*HWSZ];
__device__ float g_kt[BB*CQ*HWSZ];
__device__ float g_v [BB*CI*HWSZ];
__device__ float g_vt[BB*CI*HWSZ];
__device__ uint4 g_att4[(8ULL*HH*WW*128*2)/16];   // fp16 att [b,h,w][128]

// padded NHWC fp16 feature maps (16B aligned via uint4)
#define XP640_ELEMS (8ULL*66*66*640)
#define XP128_ELEMS (8ULL*66*66*128)
#define WSP_ELEMS   (9ULL*512*640)
__device__ uint4 g_xph4[XP640_ELEMS/8];
__device__ uint4 g_x2h4[XP128_ELEMS/8];
__device__ uint4 g_whi4[WSP_ELEMS/8];
__device__ uint4 g_wqkv4[(256*128)/8];   // packed q|k|v|pad weights, fp16

// =====================================================================
// PTX helpers (compute_103-safe: mma.sync / ldmatrix / cp.async only)
// =====================================================================
__device__ __forceinline__ uint32_t smem_u32(const void* p) {
    uint32_t a;
    asm("{ .reg .u64 t; cvta.to.shared.u64 t, %1; cvt.u32.u64 %0, t; }" : "=r"(a) : "l"(p));
    return a;
}
__device__ __forceinline__ void cpa16(uint32_t dst, const void* src) {
    asm volatile("cp.async.cg.shared.global [%0], [%1], 16;" :: "r"(dst), "l"(src) : "memory");
}
__device__ __forceinline__ void cpa_commit() {
    asm volatile("cp.async.commit_group;" ::: "memory");
}
__device__ __forceinline__ void cpa_wait1() {
    asm volatile("cp.async.wait_group 1;" ::: "memory");
}
__device__ __forceinline__ void cpa_wait0() {
    asm volatile("cp.async.wait_group 0;" ::: "memory");
}
__device__ __forceinline__ void ldsm4(uint32_t* r, uint32_t addr) {
    asm volatile("ldmatrix.sync.aligned.m8n8.x4.shared.b16 {%0,%1,%2,%3}, [%4];"
                 : "=r"(r[0]), "=r"(r[1]), "=r"(r[2]), "=r"(r[3]) : "r"(addr));
}
__device__ __forceinline__ void mma16816(float* c, const uint32_t* a, const uint32_t* b) {
    asm volatile(
        "mma.sync.aligned.m16n8k16.row.col.f32.f16.f16.f32 "
        "{%0,%1,%2,%3}, {%4,%5,%6,%7}, {%8,%9}, {%0,%1,%2,%3};"
        : "+f"(c[0]), "+f"(c[1]), "+f"(c[2]), "+f"(c[3])
        : "r"(a[0]), "r"(a[1]), "r"(a[2]), "r"(a[3]), "r"(b[0]), "r"(b[1]));
}
__device__ __forceinline__ uint32_t sw128(uint32_t off) {
    return off ^ ((off >> 3) & 0x70);
}
__device__ __forceinline__ uint4 pack8h(const float* f) {
    __half2 h0 = __floats2half2_rn(f[0], f[1]);
    __half2 h1 = __floats2half2_rn(f[2], f[3]);
    __half2 h2 = __floats2half2_rn(f[4], f[5]);
    __half2 h3 = __floats2half2_rn(f[6], f[7]);
    uint4 u;
    u.x = *(uint32_t*)&h0; u.y = *(uint32_t*)&h1;
    u.z = *(uint32_t*)&h2; u.w = *(uint32_t*)&h3;
    return u;
}

// =====================================================================
// prep: NCHW fp32 -> padded NHWC fp16 (interior only)
// =====================================================================
__global__ void __launch_bounds__(256) pad_k(
    const float* __restrict__ src, int C,
    __half* __restrict__ dh, int pitch, int colofs)
{
    __shared__ float s[64][65];
    const int y = blockIdx.x, cbase = blockIdx.y * 64, b = blockIdx.z;
    const int t = threadIdx.x;
    for (int idx = t; idx < 4096; idx += 256) {
        int icl = idx >> 6, x = idx & 63;
        s[icl][x] = src[((size_t)(b*C + cbase + icl)*64 + y)*64 + x];
    }
    __syncthreads();
    for (int idx = t; idx < 4096; idx += 256) {
        int x = idx >> 6, icl = idx & 63;
        size_t o = ((size_t)(b*66 + y + 1)*66 + (x + 1))*pitch + colofs + cbase + icl;
        dh[o] = __float2half_rn(s[icl][x]);
    }
}

__global__ void __launch_bounds__(256) zero_border_k(
    __half* __restrict__ dh, int pitch)
{
    const int total = 8 * 260 * pitch;
    for (int idx = blockIdx.x*256 + threadIdx.x; idx < total; idx += gridDim.x*256) {
        int ic = idx % pitch;
        int r  = idx / pitch;
        int b  = r / 260;
        int pos = r % 260;
        int yy, xx;
        if      (pos < 66)  { yy = 0;  xx = pos; }
        else if (pos < 132) { yy = 65; xx = pos - 66; }
        else if (pos < 196) { yy = pos - 132 + 1; xx = 0; }
        else                { yy = pos - 196 + 1; xx = 65; }
        dh[((size_t)(b*66 + yy)*66 + xx)*pitch + ic] = __float2half_rn(0.f);
    }
}

// weights: w[oc][ic][3][3] fp32 -> Wh [tap][oc][ic] fp16
__global__ void __launch_bounds__(256) wprep_k(
    const float* __restrict__ w, int Cout, int Ctot,
    __half* __restrict__ wh)
{
    const int total = Cout * Ctot * 9;
    for (int idx = blockIdx.x*256 + threadIdx.x; idx < total; idx += gridDim.x*256) {
        int ic  = idx % Ctot;
        int r   = idx / Ctot;
        int oc  = r % Cout;
        int tap = r / Cout;
        wh[(size_t)(tap*Cout + oc)*Ctot + ic] =
            __float2half_rn(w[(size_t)(oc*Ctot + ic)*9 + tap]);
    }
}

// packed qkv weights: [256 oc][128 ic] fp16 = q(16) | k(16) | v(128) | zeros(96)
__global__ void __launch_bounds__(256) wprep_qkv_k(
    const float* __restrict__ wq, const float* __restrict__ wk,
    const float* __restrict__ wv, __half* __restrict__ wh)
{
    const int total = 256 * 128;
    for (int idx = blockIdx.x*256 + threadIdx.x; idx < total; idx += gridDim.x*256) {
        int oc = idx >> 7, ic = idx & 127;
        float v = 0.f;
        if      (oc < 16)  v = wq[oc*128 + ic];
        else if (oc < 32)  v = wk[(oc-16)*128 + ic];
        else if (oc < 160) v = wv[(oc-32)*128 + ic];
        wh[idx] = __float2half_rn(v);
    }
}

// =====================================================================
// HMMA implicit-GEMM conv (frozen mainloop).
// modes: 0 = BN -> fp32 out (+ optional fp16 xpad write)
//        1 = ELU(512) -> fp32 out
//        2 = BN -> fp16 xpad ONLY
//        3 = qkv scatter (q, k + kt, v + vt)
// =====================================================================
#define TILE_B (128*128)
#define OFF_A  0
#define OFF_B  TILE_B
#define STAGE_B (2*TILE_B)
#define SM_TOTAL (3*STAGE_B)

__global__ void __launch_bounds__(256, 2) convmma_k(
    const __half* __restrict__ Xh,
    int pitch, int chunks, int ntap,
    const __half* __restrict__ Wh,
    int Ctot, int Cout,
    const float* __restrict__ p0, const float* __restrict__ p1,
    const float* __restrict__ p2, const float* __restrict__ p3,
    float* __restrict__ out, int mode,
    float* __restrict__ out2, float* __restrict__ out3,
    float* __restrict__ out3t, float* __restrict__ out2t,
    __half* __restrict__ xpad, int xpitch, int xcolofs)
{
    extern __shared__ __align__(128) char smem[];
    const uint32_t sb = smem_u32(smem);
    const int t = threadIdx.x;
    const int warp = t >> 5, lane = t & 31;
    const int nog = Cout >> 7;
    const int ocg = blockIdx.y % nog;
    const int b   = blockIdx.y / nog;
    const int y0  = blockIdx.x * 2;
    const int ocb = ocg * 128;

    const int q8 = t & 7;
    const int r0 = t >> 3;

    const int T = chunks * ntap;

    auto issue_tile = [&](int i) {
        const int c   = i / ntap;
        const int tap = i - c*ntap;
        const int dy  = (ntap == 1) ? 1 : tap / 3;
        const int dx  = (ntap == 1) ? 1 : tap - (tap/3)*3;
        const int ic0 = c * 64;
        const uint32_t base = sb + (uint32_t)(i % 3) * STAGE_B;
        #pragma unroll
        for (int p = 0; p < 4; p++) {
            const int m = r0 + 32*p;
            const uint32_t so = sw128((uint32_t)(m*128 + q8*16));
            cpa16(base + OFF_A + so,
                  Wh + (size_t)(tap*Cout + ocb + m)*Ctot + ic0 + q8*8);
            const int yl = m >> 6, x = m & 63;
            cpa16(base + OFF_B + so,
                  Xh + ((size_t)(b*66 + y0 + yl + dy)*66 + (x + dx))*pitch + ic0 + q8*8);
        }
        cpa_commit();
    };

    const int m0 = (warp >> 2) * 64;
    const int n0 = (warp & 3) * 32;
    float acc[4][4][4];
    #pragma unroll
    for (int mi = 0; mi < 4; mi++)
        #pragma unroll
        for (int nj = 0; nj < 4; nj++)
            #pragma unroll
            for (int u = 0; u < 4; u++) acc[mi][nj][u] = 0.f;

    const int arow  = lane & 15;
    const int acolb = ((lane >> 4) << 3) * 2;
    const int brow  = (lane & 7) + ((lane >> 4) << 3);
    const int bcolb = (((lane >> 3) & 1) << 3) * 2;

    issue_tile(0);
    if (T > 1) issue_tile(1);

    for (int i = 0; i < T; i++) {
        if (i + 1 < T) cpa_wait1();
        else           cpa_wait0();
        __syncthreads();
        if (i + 2 < T) issue_tile(i + 2);

        const uint32_t base = sb + (uint32_t)(i % 3) * STAGE_B;
        const uint32_t sA = base + OFF_A;
        const uint32_t sB = base + OFF_B;

        #pragma unroll
        for (int kk = 0; kk < 4; kk++) {
            const int k0b = kk * 32;
            uint32_t a[4][4], bh[2][4];
            #pragma unroll
            for (int mi = 0; mi < 4; mi++) {
                const uint32_t ro = sw128((uint32_t)((m0 + mi*16 + arow) * 128 + k0b + acolb));
                ldsm4(a[mi], sA + ro);
            }
            #pragma unroll
            for (int ni = 0; ni < 2; ni++) {
                const uint32_t ro = sw128((uint32_t)((n0 + ni*16 + brow) * 128 + k0b + bcolb));
                ldsm4(bh[ni], sB + ro);
            }
            #pragma unroll
            for (int mi = 0; mi < 4; mi++)
                #pragma unroll
                for (int nj = 0; nj < 4; nj++)
                    mma16816(acc[mi][nj], a[mi], &bh[nj >> 1][(nj & 1) * 2]);
        }
    }

    // ---- epilogue ----
    const int g  = lane >> 2;
    const int t2 = (lane & 3) * 2;
    #pragma unroll
    for (int mi = 0; mi < 4; mi++) {
        const int ocA = ocb + m0 + mi*16 + g;
        const int ocB = ocA + 8;
        float scA = 1.f, biA = 0.f, scB = 1.f, biB = 0.f;
        if (mode == 0 || mode == 2) {
            scA = p0[ocA] * rsqrtf(p3[ocA] + 1e-5f);
            biA = p1[ocA] - p2[ocA] * scA;
            scB = p0[ocB] * rsqrtf(p3[ocB] + 1e-5f);
            biB = p1[ocB] - p2[ocB] * scB;
        }
        #pragma unroll
        for (int nj = 0; nj < 4; nj++) {
            const int n  = n0 + nj*8 + t2;
            const int yl = n >> 6, x = n & 63;
            const int py = y0 + yl;
            float v0 = acc[mi][nj][0], v1 = acc[mi][nj][1];
            float v2 = acc[mi][nj][2], v3 = acc[mi][nj][3];
            if (mode == 3) {
                #pragma unroll
                for (int h = 0; h < 2; h++) {
                    const int oc = h ? ocB : ocA;
                    float u0 = h ? v2 : v0;
                    float u1 = h ? v3 : v1;
                    if (oc < 16) {
                        float bi = p0[oc];
                        *(float2*)&out[((size_t)(b*CQ + oc)*64 + py)*64 + x] =
                            make_float2(u0 + bi, u1 + bi);
                    } else if (oc < 32) {
                        const int c = oc - 16;
                        float bi = p1[c];
                        u0 += bi; u1 += bi;
                        *(float2*)&out2[((size_t)(b*CQ + c)*64 + py)*64 + x] =
                            make_float2(u0, u1);
                        out2t[((size_t)(b*CQ + c)*64 + x    )*64 + py] = u0;
                        out2t[((size_t)(b*CQ + c)*64 + x + 1)*64 + py] = u1;
                    } else if (oc < 160) {
                        const int c = oc - 32;
                        float bi = p2[c];
                        u0 += bi; u1 += bi;
                        *(float2*)&out3[((size_t)(b*CI + c)*64 + py)*64 + x] =
                            make_float2(u0, u1);
                        out3t[((size_t)(b*CI + c)*64 + x    )*64 + py] = u0;
                        out3t[((size_t)(b*CI + c)*64 + x + 1)*64 + py] = u1;
                    }
                }
                continue;
            }
            if (mode == 0 || mode == 2) {
                v0 = v0*scA + biA; v1 = v1*scA + biA;
                v2 = v2*scB + biB; v3 = v3*scB + biB;
            } else {
                if (v0 <= 0.f) v0 = 512.0f * expm1f(v0);
                if (v1 <= 0.f) v1 = 512.0f * expm1f(v1);
                if (v2 <= 0.f) v2 = 512.0f * expm1f(v2);
                if (v3 <= 0.f) v3 = 512.0f * expm1f(v3);
            }
            if (mode != 2) {
                *(float2*)&out[((size_t)(b*Cout + ocA)*64 + py)*64 + x] = make_float2(v0, v1);
                *(float2*)&out[((size_t)(b*Cout + ocB)*64 + py)*64 + x] = make_float2(v2, v3);
            }
            if ((mode == 0 || mode == 2) && xpad) {
                __half* xp = xpad + ((size_t)(b*66 + py + 1)*66 + (x + 1))*xpitch + xcolofs;
                xp[ocA]          = __float2half_rn(v0);
                xp[xpitch + ocA] = __float2half_rn(v1);
                xp[ocB]          = __float2half_rn(v2);
                xp[xpitch + ocB] = __float2half_rn(v3);
            }
        }
    }
}

// =====================================================================
// att_k: logits + softmax -> fp16 att [b,h,w][128]
// =====================================================================
__global__ void __launch_bounds__(256) att_k(
    const float* __restrict__ q, const float* __restrict__ k,
    const float* __restrict__ kt, __half* __restrict__ att)
{
    __shared__ float qs[16*64];
    __shared__ float ks[16*64];
    __shared__ float E[64*128];

    const int t = threadIdx.x;
    const int h = blockIdx.x, b = blockIdx.y;

    for (int idx = t; idx < 1024; idx += 256) {
        int c = idx >> 6, w = idx & 63;
        qs[idx] = q[((b*CQ + c)*HH + h)*WW + w];
        ks[idx] = k[((b*CQ + c)*HH + h)*WW + w];
    }
    __syncthreads();

    for (int idx = t; idx < 2048; idx += 256) {
        const int w  = idx >> 5;
        const int j4 = idx & 31;
        float4 e = make_float4(0.f, 0.f, 0.f, 0.f);
        if (j4 < 16) {
            for (int c = 0; c < 16; c++) {
                float qq = qs[c*64 + w];
                float4 kv = ((const float4*)kt)[((b*CQ + c)*WW + w)*16 + j4];
                e.x += qq * kv.x; e.y += qq * kv.y; e.z += qq * kv.z; e.w += qq * kv.w;
            }
            if ((h >> 2) == j4) ((float*)&e)[h & 3] = -INFINITY;
        } else {
            for (int c = 0; c < 16; c++) {
                float qq = qs[c*64 + w];
                float4 kv = ((const float4*)ks)[c*16 + (j4 - 16)];
                e.x += qq * kv.x; e.y += qq * kv.y; e.z += qq * kv.z; e.w += qq * kv.w;
            }
        }
        ((float4*)E)[w*32 + j4] = e;
    }
    __syncthreads();

    const int lane = t & 31, wid = t >> 5;
    for (int r = 0; r < 8; r++) {
        const int w = wid*8 + r;
        float v0 = E[w*128 + lane],      v1 = E[w*128 + lane + 32];
        float v2 = E[w*128 + lane + 64], v3 = E[w*128 + lane + 96];
        float m = fmaxf(fmaxf(v0, v1), fmaxf(v2, v3));
        #pragma unroll
        for (int s = 16; s; s >>= 1) m = fmaxf(m, __shfl_xor_sync(0xffffffffu, m, s));
        float e0 = expf(v0 - m), e1 = expf(v1 - m), e2 = expf(v2 - m), e3 = expf(v3 - m);
        float sum = e0 + e1 + e2 + e3;
        #pragma unroll
        for (int s = 16; s; s >>= 1) sum += __shfl_xor_sync(0xffffffffu, sum, s);
        float inv = 1.f / sum;
        __half* dst = att + (size_t)((b*HH + h)*WW + w)*128;
        dst[lane]      = __float2half_rn(e0*inv);
        dst[lane + 32] = __float2half_rn(e1*inv);
        dst[lane + 64] = __float2half_rn(e2*inv);
        dst[lane + 96] = __float2half_rn(e3*inv);
    }
}

// =====================================================================
// oHmma_k (store-only): raw oH -> G (scattered store-only, no RMW).
// oWmma_k: G = feat + gamma*(G_prev(oH) + oW); optional fp16 xpad write.
// =====================================================================
#define AGG_VA   0
#define AGG_AW   16384
#define AGG_SMEM (16384 + 8192)

__global__ void __launch_bounds__(256) oHmma_k(
    const __half* __restrict__ att, const float* __restrict__ vt,
    float* __restrict__ G)
{
    extern __shared__ __align__(128) char smem[];
    const uint32_t sb = smem_u32(smem);
    const int t = threadIdx.x;
    const int warp = t >> 5, lane = t & 31;
    const int w = blockIdx.x, b = blockIdx.y;

    for (int idx = t; idx < 1024; idx += 256) {
        const int c = idx >> 3, qq = idx & 7;
        float f[8];
        *(float4*)&f[0] = *(const float4*)(vt + ((size_t)(b*CI + c)*64 + w)*64 + qq*8);
        *(float4*)&f[4] = *(const float4*)(vt + ((size_t)(b*CI + c)*64 + w)*64 + qq*8 + 4);
        *(uint4*)(smem + AGG_VA + sw128((uint32_t)(c*128 + qq*16))) = pack8h(f);
    }
    for (int idx = t; idx < 512; idx += 256) {
        const int hh = idx >> 3, qq = idx & 7;
        uint4 u = *(const uint4*)(att + (size_t)((b*HH + hh)*WW + w)*128 + qq*8);
        *(uint4*)(smem + AGG_AW + sw128((uint32_t)(hh*128 + qq*16))) = u;
    }
    __syncthreads();

    const int m0 = (warp >> 2) * 64;
    const int n0 = (warp & 3) * 16;
    float acc[4][2][4];
    #pragma unroll
    for (int mi = 0; mi < 4; mi++)
        #pragma unroll
        for (int nj = 0; nj < 2; nj++)
            #pragma unroll
            for (int u = 0; u < 4; u++) acc[mi][nj][u] = 0.f;

    const int arow  = lane & 15;
    const int acolb = ((lane >> 4) << 3) * 2;
    const int brow  = (lane & 7) + ((lane >> 4) << 3);
    const int bcolb = (((lane >> 3) & 1) << 3) * 2;

    #pragma unroll
    for (int kk = 0; kk < 4; kk++) {
        const int k0b = kk * 32;
        uint32_t a[4][4], bh[4];
        #pragma unroll
        for (int mi = 0; mi < 4; mi++)
            ldsm4(a[mi], sb + AGG_VA + sw128((uint32_t)((m0 + mi*16 + arow)*128 + k0b + acolb)));
        ldsm4(bh, sb + AGG_AW + sw128((uint32_t)((n0 + brow)*128 + k0b + bcolb)));
        #pragma unroll
        for (int mi = 0; mi < 4; mi++)
            #pragma unroll
            for (int nj = 0; nj < 2; nj++)
                mma16816(acc[mi][nj], a[mi], &bh[nj*2]);
    }

    const int g  = lane >> 2;
    const int t2 = (lane & 3) * 2;
    #pragma unroll
    for (int mi = 0; mi < 4; mi++) {
        const int cA = m0 + mi*16 + g;
        const int cB = cA + 8;
        #pragma unroll
        for (int nj = 0; nj < 2; nj++) {
            const int n = n0 + nj*8 + t2;
            const size_t iA0 = ((size_t)(b*CI + cA)*64 + n)*64 + w;
            const size_t iB0 = ((size_t)(b*CI + cB)*64 + n)*64 + w;
            G[iA0]      = acc[mi][nj][0];
            G[iA0 + 64] = acc[mi][nj][1];
            G[iB0]      = acc[mi][nj][2];
            G[iB0 + 64] = acc[mi][nj][3];
        }
    }
}

__global__ void __launch_bounds__(256) oWmma_k(
    const __half* __restrict__ att, const float* __restrict__ v,
    const float* __restrict__ feat, const float* __restrict__ gamma,
    float* __restrict__ G, __half* __restrict__ xpad)
{
    extern __shared__ __align__(128) char smem[];
    const uint32_t sb = smem_u32(smem);
    const int t = threadIdx.x;
    const int warp = t >> 5, lane = t & 31;
    const int h = blockIdx.x, b = blockIdx.y;

    for (int idx = t; idx < 1024; idx += 256) {
        const int c = idx >> 3, qq = idx & 7;
        float f[8];
        *(float4*)&f[0] = *(const float4*)(v + ((size_t)(b*CI + c)*64 + h)*64 + qq*8);
        *(float4*)&f[4] = *(const float4*)(v + ((size_t)(b*CI + c)*64 + h)*64 + qq*8 + 4);
        *(uint4*)(smem + AGG_VA + sw128((uint32_t)(c*128 + qq*16))) = pack8h(f);
    }
    for (int idx = t; idx < 512; idx += 256) {
        const int w = idx >> 3, qq = idx & 7;
        uint4 u = *(const uint4*)(att + (size_t)((b*HH + h)*WW + w)*128 + 64 + qq*8);
        *(uint4*)(smem + AGG_AW + sw128((uint32_t)(w*128 + qq*16))) = u;
    }
    __syncthreads();

    const int m0 = (warp >> 2) * 64;
    const int n0 = (warp & 3) * 16;
    float acc[4][2][4];
    #pragma unroll
    for (int mi = 0; mi < 4; mi++)
        #pragma unroll
        for (int nj = 0; nj < 2; nj++)
            #pragma unroll
            for (int u = 0; u < 4; u++) acc[mi][nj][u] = 0.f;

    const int arow  = lane & 15;
    const int acolb = ((lane >> 4) << 3) * 2;
    const int brow  = (lane & 7) + ((lane >> 4) << 3);
    const int bcolb = (((lane >> 3) & 1) << 3) * 2;

    #pragma unroll
    for (int kk = 0; kk < 4; kk++) {
        const int k0b = kk * 32;
        uint32_t a[4][4], bh[4];
        #pragma unroll
        for (int mi = 0; mi < 4; mi++)
            ldsm4(a[mi], sb + AGG_VA + sw128((uint32_t)((m0 + mi*16 + arow)*128 + k0b + acolb)));
        ldsm4(bh, sb + AGG_AW + sw128((uint32_t)((n0 + brow)*128 + k0b + bcolb)));
        #pragma unroll
        for (int mi = 0; mi < 4; mi++)
            #pragma unroll
            for (int nj = 0; nj < 2; nj++)
                mma16816(acc[mi][nj], a[mi], &bh[nj*2]);
    }

    const float gm = gamma[0];
    const int g  = lane >> 2;
    const int t2 = (lane & 3) * 2;
    #pragma unroll
    for (int mi = 0; mi < 4; mi++) {
        const int cA = m0 + mi*16 + g;
        const int cB = cA + 8;
        #pragma unroll
        for (int nj = 0; nj < 2; nj++) {
            const int n = n0 + nj*8 + t2;
            const size_t iA = ((size_t)(b*CI + cA)*64 + h)*64 + n;
            const size_t iB = ((size_t)(b*CI + cB)*64 + h)*64 + n;
            float2 fA = *(const float2*)(feat + iA);
            float2 fB = *(const float2*)(feat + iB);
            float2 gA = *(const float2*)(G + iA);     // raw oH
            float2 gB = *(const float2*)(G + iB);
            float rA0 = fA.x + gm*(gA.x + acc[mi][nj][0]);
            float rA1 = fA.y + gm*(gA.y + acc[mi][nj][1]);
            float rB0 = fB.x + gm*(gB.x + acc[mi][nj][2]);
            float rB1 = fB.y + gm*(gB.y + acc[mi][nj][3]);
            *(float2*)(G + iA) = make_float2(rA0, rA1);
            *(float2*)(G + iB) = make_float2(rB0, rB1);
            if (xpad) {
                __half* xp = xpad + ((size_t)(b*66 + h + 1)*66 + (n + 1))*128;
                xp[cA]       = __float2half_rn(rA0);
                xp[128 + cA] = __float2half_rn(rA1);
                xp[cB]       = __float2half_rn(rB0);
                xp[128 + cB] = __float2half_rn(rB1);
            }
        }
    }
}

// =====================================================================
extern "C" void kernel_launch(void* const* d_in, const int* in_sizes, int n_in,
                              void* d_out, int out_size)
{
    (void)in_sizes; (void)n_in; (void)out_size;
    const float* x       = (const float*)d_in[0];
    const float* conva_w = (const float*)d_in[1];
    const float* bn1_g   = (const float*)d_in[2];
    const float* bn1_b   = (const float*)d_in[3];
    const float* bn1_m   = (const float*)d_in[4];
    const float* bn1_v   = (const float*)d_in[5];
    const float* wq      = (const float*)d_in[6];
    const float* bq      = (const float*)d_in[7];
    const float* wk      = (const float*)d_in[8];
    const float* bk      = (const float*)d_in[9];
    const float* wv      = (const float*)d_in[10];
    const float* bv      = (const float*)d_in[11];
    const float* gamma   = (const float*)d_in[12];
    const float* convb_w = (const float*)d_in[13];
    const float* bn2_g   = (const float*)d_in[14];
    const float* bn2_b   = (const float*)d_in[15];
    const float* bn2_m   = (const float*)d_in[16];
    const float* bn2_v   = (const float*)d_in[17];
    const float* bott_w  = (const float*)d_in[18];
    float* out = (float*)d_out;

    float *featA, *featB, *qb, *kb, *ktb, *vb, *vtb;
    __half* attb;
    cudaGetSymbolAddress((void**)&featA, g_featA);
    cudaGetSymbolAddress((void**)&featB, g_featB);
    cudaGetSymbolAddress((void**)&qb,    g_q);
    cudaGetSymbolAddress((void**)&kb,    g_k);
    cudaGetSymbolAddress((void**)&ktb,   g_kt);
    cudaGetSymbolAddress((void**)&vb,    g_v);
    cudaGetSymbolAddress((void**)&vtb,   g_vt);
    cudaGetSymbolAddress((void**)&attb,  g_att4);

    __half *xph, *x2h, *whi, *wqkv;
    cudaGetSymbolAddress((void**)&xph,  g_xph4);
    cudaGetSymbolAddress((void**)&x2h,  g_x2h4);
    cudaGetSymbolAddress((void**)&whi,  g_whi4);
    cudaGetSymbolAddress((void**)&wqkv, g_wqkv4);

    cudaFuncSetAttribute(oHmma_k,   cudaFuncAttributeMaxDynamicSharedMemorySize, AGG_SMEM);
    cudaFuncSetAttribute(oWmma_k,   cudaFuncAttributeMaxDynamicSharedMemorySize, AGG_SMEM);
    cudaFuncSetAttribute(convmma_k, cudaFuncAttributeMaxDynamicSharedMemorySize, SM_TOTAL);

    // ---- conv1 (512 -> 128) + BN1 -> featA (fp32) + x2h (fp16 padded) ----
    wprep_k<<<512, 256>>>(conva_w, CI, CIN, whi);
    pad_k<<<dim3(64, CIN/64, BB), 256>>>(x, CIN, xph, 640, 0);
    zero_border_k<<<1024, 256>>>(xph, 640);
    zero_border_k<<<1024, 256>>>(x2h, 128);
    convmma_k<<<dim3(32, BB), 256, SM_TOTAL>>>(xph, 640, CIN/64, 9,
                                               whi, CIN, CI,
                                               bn1_g, bn1_b, bn1_m, bn1_v,
                                               featA, 0, nullptr, nullptr, nullptr, nullptr,
                                               x2h, 128, 0);

    // ---- criss-cross attention x2 (qkv via HMMA 1x1 conv on x2h) ----
    wprep_qkv_k<<<128, 256>>>(wq, wk, wv, wqkv);
    float* F = featA;
    float* G = featB;
    for (int it = 0; it < 2; it++) {
        convmma_k<<<dim3(32, BB*2), 256, SM_TOTAL>>>(x2h, 128, CI/64, 1,
                                                     wqkv, CI, 256,
                                                     bq, bk, bv, nullptr,
                                                     qb, 3, kb, vb, vtb, ktb,
                                                     nullptr, 0, 0);
        att_k<<<dim3(HH, BB), 256>>>(qb, kb, ktb, attb);
        oHmma_k<<<dim3(WW, BB), 256, AGG_SMEM>>>(attb, vtb, G);
        oWmma_k<<<dim3(HH, BB), 256, AGG_SMEM>>>(attb, vb, F, gamma, G, x2h);
        float* tmp = F; F = G; G = tmp;
    }
    // after 2 iters: F = featA, G = featB; x2h holds fp16 of F

    // ---- convb (128 -> 128) + BN2 -> fp16 into xph cols [512,640) ----
    wprep_k<<<576, 256>>>(convb_w, CI, CI, whi);
    convmma_k<<<dim3(32, BB), 256, SM_TOTAL>>>(x2h, 128, CI/64, 9,
                                               whi, CI, CI,
                                               bn2_g, bn2_b, bn2_m, bn2_v,
                                               nullptr, 2, nullptr, nullptr, nullptr, nullptr,
                                               xph, 640, 512);

    // ---- bottleneck conv (concat 512+128 -> 512) + ELU ----
    wprep_k<<<4096, 256>>>(bott_w, CIN, CIN + CI, whi);
    convmma_k<<<dim3(32, BB*(CIN/128)), 256, SM_TOTAL>>>(xph, 640, (CIN + CI)/64, 9,
                                                         whi, CIN + CI, CIN,
                                                         nullptr, nullptr, nullptr, nullptr,
                                                         out, 1, nullptr, nullptr, nullptr, nullptr,
                                                         nullptr, 0, 0);
}